// round 3
// baseline (speedup 1.0000x reference)
#include <cuda_runtime.h>

#define Bq 4
#define Sq 4096
#define Dq 768
#define GDq 64
#define NOq 4096
#define SM1q (Sq-1)
#define ROWSq (Bq*Sq)

typedef unsigned long long u64;
typedef unsigned int u32;

// ---------------- scratch (device globals: no allocations allowed) ----------
__device__ float g_gunit[ROWSq*GDq];   // 4 MB  unit-normalized projections
__device__ float g_gn[ROWSq];          // norms
__device__ float g_sim[Bq*SM1q];       // adjacent cosine sims
__device__ int   g_idxsel[ROWSq];      // per output slot: (src_index<<1)|sel

// ---------------- K0: g = x @ W^T, gn, g_unit -------------------------------
// grid 256 blocks x 256 thr; block = 64 rows x 64 gdims; thread = 4x4 tile.
// x tile staged in 196KB smem; W (192KB) streamed from L2.
__global__ void __launch_bounds__(256) k_gemm(const float* __restrict__ x,
                                              const float* __restrict__ W){
    extern __shared__ unsigned char smraw[];
    float*  xs  = (float*)smraw;
    float4* xs4 = (float4*)smraw;
    const int rowBase = blockIdx.x * 64;
    const int tid = threadIdx.x;

    const float4* xg = (const float4*)(x + (size_t)rowBase * Dq);
    for (int idx = tid; idx < 64*192; idx += 256) xs4[idx] = xg[idx];
    __syncthreads();

    const int tx = tid & 15, ty = tid >> 4;
    const int g0 = tx*4, r0 = ty*4;
    float acc[4][4];
    #pragma unroll
    for (int i=0;i<4;i++)
        #pragma unroll
        for (int j=0;j<4;j++) acc[i][j]=0.f;

    const float4* W4 = (const float4*)W;
    #pragma unroll 4
    for (int d4 = 0; d4 < 192; d4++){
        float4 xv[4], wv[4];
        #pragma unroll
        for (int i=0;i<4;i++) xv[i] = xs4[(r0+i)*192 + d4];
        #pragma unroll
        for (int j=0;j<4;j++) wv[j] = W4[(size_t)(g0+j)*192 + d4];
        #pragma unroll
        for (int i=0;i<4;i++)
            #pragma unroll
            for (int j=0;j<4;j++){
                acc[i][j] = fmaf(xv[i].x, wv[j].x, acc[i][j]);
                acc[i][j] = fmaf(xv[i].y, wv[j].y, acc[i][j]);
                acc[i][j] = fmaf(xv[i].z, wv[j].z, acc[i][j]);
                acc[i][j] = fmaf(xv[i].w, wv[j].w, acc[i][j]);
            }
    }
    __syncthreads();              // done reading xs; reuse for norm partials

    float* part = xs;             // [64 rows][16 tx] partial sum-of-squares
    #pragma unroll
    for (int i=0;i<4;i++){
        float s = acc[i][0]*acc[i][0] + acc[i][1]*acc[i][1]
                + acc[i][2]*acc[i][2] + acc[i][3]*acc[i][3];
        part[(r0+i)*16 + tx] = s;
    }
    __syncthreads();

    float4* go = (float4*)g_gunit;
    #pragma unroll
    for (int i=0;i<4;i++){
        float s = 0.f;
        #pragma unroll
        for (int t=0;t<16;t++) s += part[(r0+i)*16 + t];  // fixed order: deterministic
        float nrm = __fsqrt_rn(s);
        if (tx == 0) g_gn[rowBase + r0 + i] = nrm;
        float denom = fmaxf(nrm, 1e-12f);
        float4 o;
        o.x = __fdiv_rn(acc[i][0], denom);
        o.y = __fdiv_rn(acc[i][1], denom);
        o.z = __fdiv_rn(acc[i][2], denom);
        o.w = __fdiv_rn(acc[i][3], denom);
        go[(size_t)(rowBase + r0 + i)*16 + tx] = o;
    }
}

// ---------------- K1: sim = dot(g_unit[s], g_unit[s+1]) ---------------------
__global__ void __launch_bounds__(256) k_sim(){
    int warp = (blockIdx.x * blockDim.x + threadIdx.x) >> 5;
    int lane = threadIdx.x & 31;
    if (warp >= Bq*SM1q) return;
    int b = warp / SM1q, s = warp % SM1q;
    const float* a = g_gunit + ((size_t)(b*Sq + s))*GDq;
    float v = fmaf(a[lane], a[lane + GDq], a[lane+32]*a[lane+32+GDq]);
    #pragma unroll
    for (int o=16;o;o>>=1) v += __shfl_xor_sync(0xffffffffu, v, o);
    if (!lane) g_sim[warp] = v;
}

// ---------------- K2: greedy matching + cap + compaction --------------------
// One block per sequence, 1024 threads.
// Sequential greedy over (sim desc, idx asc) == iterative local-max matching.
// cap r == top-r selected keys (threshold via bitonic sort of <=2048 keys).
#define SEL_SMEM 57480
__global__ void __launch_bounds__(1024) k_select(const int* __restrict__ pos_ids,
                                                 const int* __restrict__ span_ids,
                                                 const int* __restrict__ r_in,
                                                 float* __restrict__ out){
    extern __shared__ unsigned char smraw[];
    u64* key  = (u64*)smraw;            // 4096
    u64* skey = key + 4096;             // 2048
    int* ibuf = (int*)(skey + 2048);    // 32 warp sums
    int* counters = ibuf + 32;          // [0]=selCount [1]=anyAlive
    unsigned char* state = (unsigned char*)(counters + 2);  // 4096
    unsigned char* win   = state + 4096;                    // 4096

    const int tid = threadIdx.x;
    const int b   = blockIdx.x;
    int r = r_in ? r_in[0] : 1024;
    if (r < 0) r = 0;
    if (r > Sq/2) r = Sq/2;
    const int s_out = Sq - r;

    // build strict-total-order keys: sim desc, index asc
    for (int p = tid; p < Sq; p += 1024){
        if (p < SM1q){
            u32 u = __float_as_uint(g_sim[b*SM1q + p]);
            u32 m = (u & 0x80000000u) ? ~u : (u | 0x80000000u);
            key[p]   = ((u64)m << 32) | (u32)(0xFFFFFFFFu - (u32)p);
            state[p] = 0;
        } else { key[p] = 0ull; state[p] = 2; }
    }
    if (tid == 0) counters[0] = 0;
    __syncthreads();

    // iterative local-max matching (== sequential greedy with strict keys)
    while (true){
        if (tid == 0) counters[1] = 0;
        for (int p = tid; p < SM1q; p += 1024){
            unsigned char w = 0;
            if (state[p] == 0){
                u64 k = key[p];
                bool ok = true;
                if (p > 0      && state[p-1] == 0 && key[p-1] > k) ok = false;
                if (              state[p+1] == 0 && key[p+1] > k) ok = false;
                w = ok ? 1 : 0;
            }
            win[p] = w;
        }
        __syncthreads();
        for (int p = tid; p < SM1q; p += 1024) if (win[p]) state[p] = 1;
        __syncthreads();
        for (int p = tid; p < SM1q; p += 1024){
            if (state[p] == 0){
                bool blocked = (p > 0 && state[p-1] == 1) || (state[p+1] == 1);
                if (blocked) state[p] = 2;
                else         counters[1] = 1;   // benign race, all write 1
            }
        }
        __syncthreads();
        int cont = counters[1];
        __syncthreads();
        if (!cont) break;
    }

    // compact selected keys, sort ascending, threshold = r-th largest
    for (int p = tid; p < SM1q; p += 1024)
        if (state[p] == 1){ int idx = atomicAdd(&counters[0], 1); skey[idx] = key[p]; }
    __syncthreads();
    int M = counters[0];
    for (int e = tid; e < 2048; e += 1024) if (e >= M) skey[e] = 0ull;
    __syncthreads();
    for (int k = 2; k <= 2048; k <<= 1){
        for (int j = k >> 1; j > 0; j >>= 1){
            for (int e = tid; e < 2048; e += 1024){
                int pr = e ^ j;
                if (pr > e){
                    bool up = ((e & k) == 0);
                    u64 a = skey[e], c = skey[pr];
                    if ((a > c) == up){ skey[e] = c; skey[pr] = a; }
                }
            }
            __syncthreads();
        }
    }
    u64 thr = (r > 0) ? skey[2048 - r] : ~0ull;
    bool none = (r == 0);
    for (int p = tid; p < SM1q; p += 1024)
        win[p] = (!none && state[p] == 1 && key[p] >= thr) ? 1 : 0;  // final selection
    __syncthreads();

    // keep mask + block-wide exclusive scan (4 tokens / thread)
    const int i0 = tid * 4;
    int kf[4]; int lsum = 0;
    #pragma unroll
    for (int c = 0; c < 4; c++){
        int i = i0 + c;
        int kp = (i == 0) ? 1 : (win[i-1] ? 0 : 1);
        kf[c] = kp; lsum += kp;
    }
    int lane = tid & 31, wid = tid >> 5;
    int incl = lsum;
    #pragma unroll
    for (int o = 1; o < 32; o <<= 1){
        int v = __shfl_up_sync(0xffffffffu, incl, o);
        if (lane >= o) incl += v;
    }
    if (lane == 31) ibuf[wid] = incl;
    __syncthreads();
    if (tid < 32){
        int v = ibuf[tid];
        int inc2 = v;
        #pragma unroll
        for (int o = 1; o < 32; o <<= 1){
            int t2 = __shfl_up_sync(0xffffffffu, inc2, o);
            if (tid >= o) inc2 += t2;
        }
        ibuf[tid] = inc2 - v;  // exclusive warp prefix
    }
    __syncthreads();
    int pos = ibuf[wid] + (incl - lsum);

    const size_t posBase  = (size_t)Bq * s_out * (Dq + NOq);
    const size_t spanBase = posBase + (size_t)Bq * s_out;
    #pragma unroll
    for (int c = 0; c < 4; c++){
        int i = i0 + c;
        if (kf[c]){
            if (pos < s_out){
                int sel = (i < SM1q && win[i]) ? 1 : 0;
                g_idxsel[b*Sq + pos] = (i << 1) | sel;
                out[posBase  + (size_t)b*s_out + pos] = (float)pos_ids[b*Sq + i];
                int sp = span_ids[b*Sq + i] + (sel ? span_ids[b*Sq + i + 1] : 0);
                out[spanBase + (size_t)b*s_out + pos] = (float)sp;
            }
            pos++;
        }
    }
}

// ---------------- K3: gather + weighted merge (the bandwidth kernel) --------
__global__ void __launch_bounds__(256) k_gather(const float* __restrict__ x,
                                                const float* __restrict__ src,
                                                const int* __restrict__ r_in,
                                                float* __restrict__ out){
    int r = r_in ? r_in[0] : 1024;
    if (r < 0) r = 0;
    if (r > Sq/2) r = Sq/2;
    const int s_out = Sq - r;
    const int b = blockIdx.x / Sq;
    const int j = blockIdx.x - b*Sq;
    if (j >= s_out) return;

    const int packed = g_idxsel[b*Sq + j];
    const int i   = packed >> 1;
    const int sel = packed & 1;
    const size_t tin  = (size_t)b*Sq + i;
    const size_t tout = (size_t)b*s_out + j;

    const float4* x0 = (const float4*)(x + tin*Dq);
    float4* xo = (float4*)(out + tout*Dq);
    const float4* s0 = (const float4*)(src + tin*NOq);
    float4* so = (float4*)(out + (size_t)Bq*s_out*Dq + tout*NOq);

    if (sel){
        const float wi = g_gn[tin], wj = g_gn[tin+1];
        const float inv = 1.f / (wi + wj + 1e-8f);
        const float4* x1 = (const float4*)(x + (tin+1)*Dq);
        for (int t = threadIdx.x; t < Dq/4; t += 256){
            float4 a = x0[t], c = x1[t], o;
            o.x = (wi*a.x + wj*c.x)*inv; o.y = (wi*a.y + wj*c.y)*inv;
            o.z = (wi*a.z + wj*c.z)*inv; o.w = (wi*a.w + wj*c.w)*inv;
            xo[t] = o;
        }
        const float4* s1 = (const float4*)(src + (tin+1)*NOq);
        for (int t = threadIdx.x; t < NOq/4; t += 256){
            float4 a = s0[t], c = s1[t], o;
            o.x = a.x+c.x; o.y = a.y+c.y; o.z = a.z+c.z; o.w = a.w+c.w;
            so[t] = o;
        }
    } else {
        for (int t = threadIdx.x; t < Dq/4;  t += 256) xo[t] = x0[t];
        for (int t = threadIdx.x; t < NOq/4; t += 256) so[t] = s0[t];
    }
}

// ---------------- launch ----------------------------------------------------
extern "C" void kernel_launch(void* const* d_in, const int* in_sizes, int n_in,
                              void* d_out, int out_size){
    (void)in_sizes; (void)out_size;
    const float* x    = (const float*)d_in[0];
    const float* src  = (const float*)d_in[1];
    const int*   pos  = (const int*)d_in[2];
    const int*   span = (const int*)d_in[3];
    const float* W    = (const float*)d_in[4];
    const int*   r    = (n_in >= 6) ? (const int*)d_in[5] : nullptr;
    float* out = (float*)d_out;

    cudaFuncSetAttribute(k_gemm,   cudaFuncAttributeMaxDynamicSharedMemorySize, 196608);
    cudaFuncSetAttribute(k_select, cudaFuncAttributeMaxDynamicSharedMemorySize, SEL_SMEM);

    k_gemm  <<<256, 256, 196608>>>(x, W);
    k_sim   <<<2048, 256>>>();
    k_select<<<Bq, 1024, SEL_SMEM>>>(pos, span, r, out);
    k_gather<<<Bq*Sq, 256>>>(x, src, r, out);
}

// round 4
// speedup vs baseline: 1.7583x; 1.7583x over previous
#include <cuda_runtime.h>

#define Bq 4
#define Sq 4096
#define Dq 768
#define GDq 64
#define NOq 4096
#define SM1q (Sq-1)
#define ROWSq (Bq*Sq)

typedef unsigned long long u64;
typedef unsigned int u32;

// ---------------- scratch (device globals: no allocations allowed) ----------
__device__ float g_gunit[ROWSq*GDq];   // 4 MB  unit-normalized projections
__device__ float g_gn[ROWSq];          // norms
__device__ float g_sim[Bq*SM1q];       // adjacent cosine sims
__device__ int   g_idxsel[ROWSq];      // per output slot: (src_index<<1)|sel

// ---------------- K0: g = x @ W^T, gn, g_unit -------------------------------
// 256 blocks x 256 thr; block = 64 rows x 64 gdims; thread tile 4x4.
// x tile (192KB) in smem; W staged per-32d chunk (8KB) in smem, prefetched.
// Inner loop uses packed fma.rn.f32x2 (FFMA2) -> half the FFMA issue count.
// W chunk smem layout per dd2 (float2-of-d) row of 512B:
//   byte(g) = ((g>>1)&1)*256 + (g>>2)*16 + (g&1)*8
// so lane tx reads gd 4tx..4tx+3 with two LDS.128 at tx*16 and 256+tx*16
// (2-way bank conflict, 2 cyc each).
#define GEMM_SMEM (196608 + 8192)

__device__ __forceinline__ int wgoff(int g){
    return ((g >> 1) & 1) * 256 + (g >> 2) * 16 + (g & 1) * 8;
}

__global__ void __launch_bounds__(256) k_gemm(const float* __restrict__ x,
                                              const float* __restrict__ W){
    extern __shared__ unsigned char smraw[];
    float4* xs4 = (float4*)smraw;                 // 64 rows x 192 float4
    unsigned char* wsb = smraw + 196608;          // 16 dd2-rows x 512B
    const int rowBase = blockIdx.x * 64;
    const int tid = threadIdx.x;

    // stage x tile
    const float4* xg = (const float4*)(x + (size_t)rowBase * Dq);
    for (int idx = tid; idx < 64*192; idx += 256) xs4[idx] = xg[idx];

    const int tx = tid & 15, ty = tid >> 4;
    const int r0 = ty * 4;

    u64 acc2[4][4];
    #pragma unroll
    for (int i=0;i<4;i++)
        #pragma unroll
        for (int j=0;j<4;j++) acc2[i][j] = 0ull;   // bits 0 == (0.f,0.f)

    const float4* W4 = (const float4*)W;
    const int gA = tid >> 3,          k4A = tid & 7;          // element A of chunk
    const int gB = (tid + 256) >> 3,  k4B = (tid + 256) & 7;  // element B

    // prefetch chunk 0
    float4 vA = W4[(size_t)gA*192 + k4A];
    float4 vB = W4[(size_t)gB*192 + k4B];

    for (int c = 0; c < 24; c++){
        __syncthreads();                          // ws free (prev chunk consumed)
        {   // store staged chunk into ws
            unsigned char* pA = wsb + wgoff(gA);
            *(float2*)(pA + (k4A*2  )*512) = make_float2(vA.x, vA.y);
            *(float2*)(pA + (k4A*2+1)*512) = make_float2(vA.z, vA.w);
            unsigned char* pB = wsb + wgoff(gB);
            *(float2*)(pB + (k4B*2  )*512) = make_float2(vB.x, vB.y);
            *(float2*)(pB + (k4B*2+1)*512) = make_float2(vB.z, vB.w);
        }
        if (c + 1 < 24){                          // prefetch next chunk (hidden)
            vA = W4[(size_t)gA*192 + (c+1)*8 + k4A];
            vB = W4[(size_t)gB*192 + (c+1)*8 + k4B];
        }
        __syncthreads();

        #pragma unroll
        for (int dd4 = 0; dd4 < 8; dd4++){        // each dd4 covers 4 d (2 dd2)
            ulonglong2 xv[4];
            #pragma unroll
            for (int i=0;i<4;i++)
                xv[i] = *(const ulonglong2*)&xs4[(r0+i)*192 + c*8 + dd4];

            const unsigned char* wp = wsb + (dd4*2)*512 + tx*16;
            ulonglong2 wa01 = *(const ulonglong2*)(wp);
            ulonglong2 wa23 = *(const ulonglong2*)(wp + 256);
            ulonglong2 wb01 = *(const ulonglong2*)(wp + 512);
            ulonglong2 wb23 = *(const ulonglong2*)(wp + 768);
            u64 wav[4] = {wa01.x, wa01.y, wa23.x, wa23.y};
            u64 wbv[4] = {wb01.x, wb01.y, wb23.x, wb23.y};

            #pragma unroll
            for (int i=0;i<4;i++){
                #pragma unroll
                for (int j=0;j<4;j++){
                    asm("fma.rn.f32x2 %0, %1, %2, %0;"
                        : "+l"(acc2[i][j]) : "l"(xv[i].x), "l"(wav[j]));
                    asm("fma.rn.f32x2 %0, %1, %2, %0;"
                        : "+l"(acc2[i][j]) : "l"(xv[i].y), "l"(wbv[j]));
                }
            }
        }
    }

    // unpack: acc = lo + hi (deterministic, exact fp32)
    float acc[4][4];
    #pragma unroll
    for (int i=0;i<4;i++)
        #pragma unroll
        for (int j=0;j<4;j++){
            u64 v = acc2[i][j];
            acc[i][j] = __uint_as_float((u32)v) + __uint_as_float((u32)(v >> 32));
        }

    __syncthreads();              // done reading xs; reuse for norm partials
    float* part = (float*)smraw;  // [64 rows][16 tx]
    #pragma unroll
    for (int i=0;i<4;i++){
        float s = acc[i][0]*acc[i][0] + acc[i][1]*acc[i][1]
                + acc[i][2]*acc[i][2] + acc[i][3]*acc[i][3];
        part[(r0+i)*16 + tx] = s;
    }
    __syncthreads();

    const int g0 = tx*4;
    float4* go = (float4*)g_gunit;
    #pragma unroll
    for (int i=0;i<4;i++){
        float s = 0.f;
        #pragma unroll
        for (int t=0;t<16;t++) s += part[(r0+i)*16 + t];  // fixed order
        float nrm = __fsqrt_rn(s);
        if (tx == 0) g_gn[rowBase + r0 + i] = nrm;
        float denom = fmaxf(nrm, 1e-12f);
        float4 o;
        o.x = __fdiv_rn(acc[i][0], denom);
        o.y = __fdiv_rn(acc[i][1], denom);
        o.z = __fdiv_rn(acc[i][2], denom);
        o.w = __fdiv_rn(acc[i][3], denom);
        go[(size_t)(rowBase + r0 + i)*16 + tx] = o;
    }
    (void)g0;
}

// ---------------- K1: sim = dot(g_unit[s], g_unit[s+1]) ---------------------
__global__ void __launch_bounds__(256) k_sim(){
    int warp = (blockIdx.x * blockDim.x + threadIdx.x) >> 5;
    int lane = threadIdx.x & 31;
    if (warp >= Bq*SM1q) return;
    int b = warp / SM1q, s = warp % SM1q;
    const float* a = g_gunit + ((size_t)(b*Sq + s))*GDq;
    float v = fmaf(a[lane], a[lane + GDq], a[lane+32]*a[lane+32+GDq]);
    #pragma unroll
    for (int o=16;o;o>>=1) v += __shfl_xor_sync(0xffffffffu, v, o);
    if (!lane) g_sim[warp] = v;
}

// ---------------- K2: greedy matching + cap + compaction --------------------
#define SEL_SMEM 57480
__global__ void __launch_bounds__(1024) k_select(const int* __restrict__ pos_ids,
                                                 const int* __restrict__ span_ids,
                                                 const int* __restrict__ r_in,
                                                 float* __restrict__ out){
    extern __shared__ unsigned char smraw[];
    u64* key  = (u64*)smraw;            // 4096
    u64* skey = key + 4096;             // 2048
    int* ibuf = (int*)(skey + 2048);    // 32 warp sums
    int* counters = ibuf + 32;          // [0]=selCount [1]=anyAlive
    unsigned char* state = (unsigned char*)(counters + 2);  // 4096
    unsigned char* win   = state + 4096;                    // 4096

    const int tid = threadIdx.x;
    const int b   = blockIdx.x;
    int r = r_in ? r_in[0] : 1024;
    if (r < 0) r = 0;
    if (r > Sq/2) r = Sq/2;
    const int s_out = Sq - r;

    for (int p = tid; p < Sq; p += 1024){
        if (p < SM1q){
            u32 u = __float_as_uint(g_sim[b*SM1q + p]);
            u32 m = (u & 0x80000000u) ? ~u : (u | 0x80000000u);
            key[p]   = ((u64)m << 32) | (u32)(0xFFFFFFFFu - (u32)p);
            state[p] = 0;
        } else { key[p] = 0ull; state[p] = 2; }
    }
    if (tid == 0) counters[0] = 0;
    __syncthreads();

    while (true){
        if (tid == 0) counters[1] = 0;
        for (int p = tid; p < SM1q; p += 1024){
            unsigned char w = 0;
            if (state[p] == 0){
                u64 k = key[p];
                bool ok = true;
                if (p > 0      && state[p-1] == 0 && key[p-1] > k) ok = false;
                if (              state[p+1] == 0 && key[p+1] > k) ok = false;
                w = ok ? 1 : 0;
            }
            win[p] = w;
        }
        __syncthreads();
        for (int p = tid; p < SM1q; p += 1024) if (win[p]) state[p] = 1;
        __syncthreads();
        for (int p = tid; p < SM1q; p += 1024){
            if (state[p] == 0){
                bool blocked = (p > 0 && state[p-1] == 1) || (state[p+1] == 1);
                if (blocked) state[p] = 2;
                else         counters[1] = 1;
            }
        }
        __syncthreads();
        int cont = counters[1];
        __syncthreads();
        if (!cont) break;
    }

    for (int p = tid; p < SM1q; p += 1024)
        if (state[p] == 1){ int idx = atomicAdd(&counters[0], 1); skey[idx] = key[p]; }
    __syncthreads();
    int M = counters[0];
    for (int e = tid; e < 2048; e += 1024) if (e >= M) skey[e] = 0ull;
    __syncthreads();
    for (int k = 2; k <= 2048; k <<= 1){
        for (int j = k >> 1; j > 0; j >>= 1){
            for (int e = tid; e < 2048; e += 1024){
                int pr = e ^ j;
                if (pr > e){
                    bool up = ((e & k) == 0);
                    u64 a = skey[e], c = skey[pr];
                    if ((a > c) == up){ skey[e] = c; skey[pr] = a; }
                }
            }
            __syncthreads();
        }
    }
    u64 thr = (r > 0) ? skey[2048 - r] : ~0ull;
    bool none = (r == 0);
    for (int p = tid; p < SM1q; p += 1024)
        win[p] = (!none && state[p] == 1 && key[p] >= thr) ? 1 : 0;
    __syncthreads();

    const int i0 = tid * 4;
    int kf[4]; int lsum = 0;
    #pragma unroll
    for (int c = 0; c < 4; c++){
        int i = i0 + c;
        int kp = (i == 0) ? 1 : (win[i-1] ? 0 : 1);
        kf[c] = kp; lsum += kp;
    }
    int lane = tid & 31, wid = tid >> 5;
    int incl = lsum;
    #pragma unroll
    for (int o = 1; o < 32; o <<= 1){
        int v = __shfl_up_sync(0xffffffffu, incl, o);
        if (lane >= o) incl += v;
    }
    if (lane == 31) ibuf[wid] = incl;
    __syncthreads();
    if (tid < 32){
        int v = ibuf[tid];
        int inc2 = v;
        #pragma unroll
        for (int o = 1; o < 32; o <<= 1){
            int t2 = __shfl_up_sync(0xffffffffu, inc2, o);
            if (tid >= o) inc2 += t2;
        }
        ibuf[tid] = inc2 - v;
    }
    __syncthreads();
    int pos = ibuf[wid] + (incl - lsum);

    const size_t posBase  = (size_t)Bq * s_out * (Dq + NOq);
    const size_t spanBase = posBase + (size_t)Bq * s_out;
    #pragma unroll
    for (int c = 0; c < 4; c++){
        int i = i0 + c;
        if (kf[c]){
            if (pos < s_out){
                int sel = (i < SM1q && win[i]) ? 1 : 0;
                g_idxsel[b*Sq + pos] = (i << 1) | sel;
                out[posBase  + (size_t)b*s_out + pos] = (float)pos_ids[b*Sq + i];
                int sp = span_ids[b*Sq + i] + (sel ? span_ids[b*Sq + i + 1] : 0);
                out[spanBase + (size_t)b*s_out + pos] = (float)sp;
            }
            pos++;
        }
    }
}

// ---------------- K3: gather + weighted merge (the bandwidth kernel) --------
__global__ void __launch_bounds__(256) k_gather(const float* __restrict__ x,
                                                const float* __restrict__ src,
                                                const int* __restrict__ r_in,
                                                float* __restrict__ out){
    int r = r_in ? r_in[0] : 1024;
    if (r < 0) r = 0;
    if (r > Sq/2) r = Sq/2;
    const int s_out = Sq - r;
    const int b = blockIdx.x / Sq;
    const int j = blockIdx.x - b*Sq;
    if (j >= s_out) return;

    const int packed = g_idxsel[b*Sq + j];
    const int i   = packed >> 1;
    const int sel = packed & 1;
    const size_t tin  = (size_t)b*Sq + i;
    const size_t tout = (size_t)b*s_out + j;

    const float4* x0 = (const float4*)(x + tin*Dq);
    float4* xo = (float4*)(out + tout*Dq);
    const float4* s0 = (const float4*)(src + tin*NOq);
    float4* so = (float4*)(out + (size_t)Bq*s_out*Dq + tout*NOq);

    if (sel){
        const float wi = g_gn[tin], wj = g_gn[tin+1];
        const float inv = 1.f / (wi + wj + 1e-8f);
        const float4* x1 = (const float4*)(x + (tin+1)*Dq);
        for (int t = threadIdx.x; t < Dq/4; t += 256){
            float4 a = x0[t], c = x1[t], o;
            o.x = (wi*a.x + wj*c.x)*inv; o.y = (wi*a.y + wj*c.y)*inv;
            o.z = (wi*a.z + wj*c.z)*inv; o.w = (wi*a.w + wj*c.w)*inv;
            xo[t] = o;
        }
        const float4* s1 = (const float4*)(src + (tin+1)*NOq);
        for (int t = threadIdx.x; t < NOq/4; t += 256){
            float4 a = s0[t], c = s1[t], o;
            o.x = a.x+c.x; o.y = a.y+c.y; o.z = a.z+c.z; o.w = a.w+c.w;
            so[t] = o;
        }
    } else {
        for (int t = threadIdx.x; t < Dq/4;  t += 256) xo[t] = x0[t];
        for (int t = threadIdx.x; t < NOq/4; t += 256) so[t] = s0[t];
    }
}

// ---------------- launch ----------------------------------------------------
extern "C" void kernel_launch(void* const* d_in, const int* in_sizes, int n_in,
                              void* d_out, int out_size){
    (void)in_sizes; (void)out_size;
    const float* x    = (const float*)d_in[0];
    const float* src  = (const float*)d_in[1];
    const int*   pos  = (const int*)d_in[2];
    const int*   span = (const int*)d_in[3];
    const float* W    = (const float*)d_in[4];
    const int*   r    = (n_in >= 6) ? (const int*)d_in[5] : nullptr;
    float* out = (float*)d_out;

    cudaFuncSetAttribute(k_gemm,   cudaFuncAttributeMaxDynamicSharedMemorySize, GEMM_SMEM);
    cudaFuncSetAttribute(k_select, cudaFuncAttributeMaxDynamicSharedMemorySize, SEL_SMEM);

    k_gemm  <<<256, 256, GEMM_SMEM>>>(x, W);
    k_sim   <<<2048, 256>>>();
    k_select<<<Bq, 1024, SEL_SMEM>>>(pos, span, r, out);
    k_gather<<<Bq*Sq, 256>>>(x, src, r, out);
}

// round 5
// speedup vs baseline: 2.0224x; 1.1502x over previous
#include <cuda_runtime.h>

#define Bq 4
#define Sq 4096
#define Dq 768
#define GDq 64
#define NOq 4096
#define SM1q (Sq-1)
#define ROWSq (Bq*Sq)

typedef unsigned long long u64;
typedef unsigned int u32;

// ---------------- scratch (device globals: no allocations allowed) ----------
__device__ float g_gunit[ROWSq*GDq];   // 4 MB  unit-normalized projections
__device__ float g_gn[ROWSq];          // norms
__device__ float g_sim[Bq*SM1q];       // adjacent cosine sims
__device__ int   g_idxsel[ROWSq];      // per output slot: (src_index<<1)|sel

// ---------------- K0: g = x @ W^T, gn, g_unit -------------------------------
// 256 blocks x 256 thr; block = 64 rows x 64 gdims; thread tile 4x4.
// k-chunked (32 d per chunk), DOUBLE-BUFFERED x(8KB)+W(8KB) smem -> 32KB total
// -> 2 blocks/SM, whole grid resident in one wave. Inner loop = packed
// fma.rn.f32x2, identical accumulation order to the R4 kernel (bit-identical
// sims -> identical selection).
#define GEMM_SMEM 32768

__device__ __forceinline__ int wgoff(int g){
    return ((g >> 1) & 1) * 256 + (g >> 2) * 16 + (g & 1) * 8;
}

__global__ void __launch_bounds__(256, 2) k_gemm(const float* __restrict__ x,
                                                 const float* __restrict__ W){
    extern __shared__ unsigned char smraw[];
    float4* xs4 = (float4*)smraw;                 // 2 bufs x 64 rows x 8 float4
    unsigned char* wsb = smraw + 16384;           // 2 bufs x 16 dd2-rows x 512B
    const int rowBase = blockIdx.x * 64;
    const int tid = threadIdx.x;

    const int tx = tid & 15, ty = tid >> 4;
    const int r0 = ty * 4;

    u64 acc2[4][4];
    #pragma unroll
    for (int i=0;i<4;i++)
        #pragma unroll
        for (int j=0;j<4;j++) acc2[i][j] = 0ull;

    const float4* xg = (const float4*)x;
    const float4* W4 = (const float4*)W;
    const int xrowA = tid >> 3,  xd4A = tid & 7;          // x stage elem A
    const int xrowB = xrowA + 32;                         // x stage elem B (tid+256)
    const int gA = tid >> 3,          k4A = tid & 7;      // W stage elem A
    const int gB = (tid + 256) >> 3,  k4B = (tid + 256) & 7;

    // prefetch chunk 0
    float4 xa = xg[(size_t)(rowBase + xrowA)*192 + xd4A];
    float4 xb = xg[(size_t)(rowBase + xrowB)*192 + xd4A];
    float4 vA = W4[(size_t)gA*192 + k4A];
    float4 vB = W4[(size_t)gB*192 + k4B];

    // store chunk 0 into buffer 0
    xs4[xrowA*8 + xd4A] = xa;
    xs4[xrowB*8 + xd4A] = xb;
    {
        unsigned char* pA = wsb + wgoff(gA);
        *(float2*)(pA + (k4A*2  )*512) = make_float2(vA.x, vA.y);
        *(float2*)(pA + (k4A*2+1)*512) = make_float2(vA.z, vA.w);
        unsigned char* pB = wsb + wgoff(gB);
        *(float2*)(pB + (k4B*2  )*512) = make_float2(vB.x, vB.y);
        *(float2*)(pB + (k4B*2+1)*512) = make_float2(vB.z, vB.w);
    }
    __syncthreads();

    for (int c = 0; c < 24; c++){
        const int buf = c & 1;
        if (c + 1 < 24){   // prefetch next chunk into regs (overlaps compute)
            xa = xg[(size_t)(rowBase + xrowA)*192 + (c+1)*8 + xd4A];
            xb = xg[(size_t)(rowBase + xrowB)*192 + (c+1)*8 + xd4A];
            vA = W4[(size_t)gA*192 + (c+1)*8 + k4A];
            vB = W4[(size_t)gB*192 + (c+1)*8 + k4B];
        }

        const float4* xsb = xs4 + buf*512;
        const unsigned char* wb = wsb + buf*8192;
        #pragma unroll
        for (int dd4 = 0; dd4 < 8; dd4++){
            ulonglong2 xv[4];
            #pragma unroll
            for (int i=0;i<4;i++)
                xv[i] = *(const ulonglong2*)&xsb[(r0+i)*8 + dd4];

            const unsigned char* wp = wb + (dd4*2)*512 + tx*16;
            ulonglong2 wa01 = *(const ulonglong2*)(wp);
            ulonglong2 wa23 = *(const ulonglong2*)(wp + 256);
            ulonglong2 wb01 = *(const ulonglong2*)(wp + 512);
            ulonglong2 wb23 = *(const ulonglong2*)(wp + 768);
            u64 wav[4] = {wa01.x, wa01.y, wa23.x, wa23.y};
            u64 wbv[4] = {wb01.x, wb01.y, wb23.x, wb23.y};

            #pragma unroll
            for (int i=0;i<4;i++){
                #pragma unroll
                for (int j=0;j<4;j++){
                    asm("fma.rn.f32x2 %0, %1, %2, %0;"
                        : "+l"(acc2[i][j]) : "l"(xv[i].x), "l"(wav[j]));
                    asm("fma.rn.f32x2 %0, %1, %2, %0;"
                        : "+l"(acc2[i][j]) : "l"(xv[i].y), "l"(wbv[j]));
                }
            }
        }

        if (c + 1 < 24){
            __syncthreads();                      // all done reading other buf
            const int nb = (c + 1) & 1;
            xs4[nb*512 + xrowA*8 + xd4A] = xa;
            xs4[nb*512 + xrowB*8 + xd4A] = xb;
            unsigned char* pA = wsb + nb*8192 + wgoff(gA);
            *(float2*)(pA + (k4A*2  )*512) = make_float2(vA.x, vA.y);
            *(float2*)(pA + (k4A*2+1)*512) = make_float2(vA.z, vA.w);
            unsigned char* pB = wsb + nb*8192 + wgoff(gB);
            *(float2*)(pB + (k4B*2  )*512) = make_float2(vB.x, vB.y);
            *(float2*)(pB + (k4B*2+1)*512) = make_float2(vB.z, vB.w);
            __syncthreads();
        }
    }

    // unpack: acc = lo + hi (deterministic, exact fp32)
    float acc[4][4];
    #pragma unroll
    for (int i=0;i<4;i++)
        #pragma unroll
        for (int j=0;j<4;j++){
            u64 v = acc2[i][j];
            acc[i][j] = __uint_as_float((u32)v) + __uint_as_float((u32)(v >> 32));
        }

    __syncthreads();              // smem free; reuse for norm partials
    float* part = (float*)smraw;  // [64 rows][16 tx]
    #pragma unroll
    for (int i=0;i<4;i++){
        float s = acc[i][0]*acc[i][0] + acc[i][1]*acc[i][1]
                + acc[i][2]*acc[i][2] + acc[i][3]*acc[i][3];
        part[(r0+i)*16 + tx] = s;
    }
    __syncthreads();

    float4* go = (float4*)g_gunit;
    #pragma unroll
    for (int i=0;i<4;i++){
        float s = 0.f;
        #pragma unroll
        for (int t=0;t<16;t++) s += part[(r0+i)*16 + t];  // fixed order
        float nrm = __fsqrt_rn(s);
        if (tx == 0) g_gn[rowBase + r0 + i] = nrm;
        float denom = fmaxf(nrm, 1e-12f);
        float4 o;
        o.x = __fdiv_rn(acc[i][0], denom);
        o.y = __fdiv_rn(acc[i][1], denom);
        o.z = __fdiv_rn(acc[i][2], denom);
        o.w = __fdiv_rn(acc[i][3], denom);
        go[(size_t)(rowBase + r0 + i)*16 + tx] = o;
    }
}

// ---------------- K1: sim = dot(g_unit[s], g_unit[s+1]) ---------------------
__global__ void __launch_bounds__(256) k_sim(){
    int warp = (blockIdx.x * blockDim.x + threadIdx.x) >> 5;
    int lane = threadIdx.x & 31;
    if (warp >= Bq*SM1q) return;
    int b = warp / SM1q, s = warp % SM1q;
    const float* a = g_gunit + ((size_t)(b*Sq + s))*GDq;
    float v = fmaf(a[lane], a[lane + GDq], a[lane+32]*a[lane+32+GDq]);
    #pragma unroll
    for (int o=16;o;o>>=1) v += __shfl_xor_sync(0xffffffffu, v, o);
    if (!lane) g_sim[warp] = v;
}

// ---------------- K2: greedy matching + cap + compaction --------------------
// One block per sequence, 1024 threads, 4 pair-slots per thread IN REGISTERS.
// Iterative local-max matching (== sequential greedy with strict keys);
// per round only boundary (key,alive)/(win) exchanged through smem.
#define SEL_SMEM 24832
__global__ void __launch_bounds__(1024) k_select(const int* __restrict__ pos_ids,
                                                 const int* __restrict__ span_ids,
                                                 const int* __restrict__ r_in,
                                                 float* __restrict__ out){
    extern __shared__ unsigned char smraw[];
    u64* ek0 = (u64*)smraw;                       // [1024] key of slot0
    u64* ek3 = (u64*)(smraw + 8192);              // [1024] key of slot3
    u64* skey = (u64*)smraw;                      // [2048] aliases ek0/ek3 (after rounds)
    unsigned char* ea0 = smraw + 16384;           // alive of slot0
    unsigned char* ea3 = smraw + 17408;
    unsigned char* ew0 = smraw + 18432;           // win of slot0
    unsigned char* ew3 = smraw + 19456;
    unsigned char* win = smraw + 20480;           // [4096] final selection
    int* ibuf     = (int*)(smraw + 24576);        // [32]
    int* counters = (int*)(smraw + 24704);        // [0]=selCount

    const int tid = threadIdx.x;
    const int b   = blockIdx.x;
    int r = r_in ? r_in[0] : 1024;
    if (r < 0) r = 0;
    if (r > Sq/2) r = Sq/2;
    const int s_out = Sq - r;

    // build strict-total-order keys: sim desc, index asc
    u64 k0,k1,k2,k3;
    bool a0,a1,a2,a3;
    {
        const int p0 = tid*4;
        float4 sv;
        // p0..p0+3 ; p0+3 may be 4095 (invalid)
        sv.x = (p0+0 < SM1q) ? g_sim[b*SM1q + p0+0] : 0.f;
        sv.y = (p0+1 < SM1q) ? g_sim[b*SM1q + p0+1] : 0.f;
        sv.z = (p0+2 < SM1q) ? g_sim[b*SM1q + p0+2] : 0.f;
        sv.w = (p0+3 < SM1q) ? g_sim[b*SM1q + p0+3] : 0.f;
        u32 u;
        u = __float_as_uint(sv.x); u = (u & 0x80000000u) ? ~u : (u | 0x80000000u);
        k0 = ((u64)u << 32) | (u32)(0xFFFFFFFFu - (u32)(p0+0));
        u = __float_as_uint(sv.y); u = (u & 0x80000000u) ? ~u : (u | 0x80000000u);
        k1 = ((u64)u << 32) | (u32)(0xFFFFFFFFu - (u32)(p0+1));
        u = __float_as_uint(sv.z); u = (u & 0x80000000u) ? ~u : (u | 0x80000000u);
        k2 = ((u64)u << 32) | (u32)(0xFFFFFFFFu - (u32)(p0+2));
        u = __float_as_uint(sv.w); u = (u & 0x80000000u) ? ~u : (u | 0x80000000u);
        k3 = ((u64)u << 32) | (u32)(0xFFFFFFFFu - (u32)(p0+3));
        a0 = (p0+0 < SM1q); a1 = (p0+1 < SM1q);
        a2 = (p0+2 < SM1q); a3 = (p0+3 < SM1q);
        if (!a3) k3 = 0ull;
    }
    bool s0=false, s1=false, s2=false, s3=false;
    if (tid == 0) counters[0] = 0;

    while (true){
        ek0[tid] = k0; ea0[tid] = a0;
        ek3[tid] = k3; ea3[tid] = a3;
        __syncthreads();
        u64 lk = 0, rk = 0; bool la = false, ra = false;
        if (tid > 0)    { lk = ek3[tid-1]; la = ea3[tid-1] != 0; }
        if (tid < 1023) { rk = ek0[tid+1]; ra = ea0[tid+1] != 0; }

        bool w0 = a0 && !(la && lk > k0) && !(a1 && k1 > k0);
        bool w1 = a1 && !(a0 && k0 > k1) && !(a2 && k2 > k1);
        bool w2 = a2 && !(a1 && k1 > k2) && !(a3 && k3 > k2);
        bool w3 = a3 && !(a2 && k2 > k3) && !(ra && rk > k3);

        ew0[tid] = w0; ew3[tid] = w3;
        __syncthreads();
        bool lw = (tid > 0)    ? (ew3[tid-1] != 0) : false;
        bool rw = (tid < 1023) ? (ew0[tid+1] != 0) : false;

        s0 |= w0; s1 |= w1; s2 |= w2; s3 |= w3;
        a0 = a0 && !w0 && !lw && !w1;
        a1 = a1 && !w1 && !w0 && !w2;
        a2 = a2 && !w2 && !w1 && !w3;
        a3 = a3 && !w3 && !w2 && !rw;

        int cont = __syncthreads_or((int)(a0|a1|a2|a3));
        if (!cont) break;
    }

    // compact selected keys into skey (aliases ek*, rounds are over)
    __syncthreads();
    {
        if (s0){ int i2 = atomicAdd(counters, 1); skey[i2] = k0; }
        if (s1){ int i2 = atomicAdd(counters, 1); skey[i2] = k1; }
        if (s2){ int i2 = atomicAdd(counters, 1); skey[i2] = k2; }
        if (s3){ int i2 = atomicAdd(counters, 1); skey[i2] = k3; }
    }
    __syncthreads();
    int M = counters[0];
    for (int e = tid; e < 2048; e += 1024) if (e >= M) skey[e] = 0ull;
    __syncthreads();
    for (int kk = 2; kk <= 2048; kk <<= 1){
        for (int j = kk >> 1; j > 0; j >>= 1){
            for (int e = tid; e < 2048; e += 1024){
                int pr = e ^ j;
                if (pr > e){
                    bool up = ((e & kk) == 0);
                    u64 av = skey[e], cv = skey[pr];
                    if ((av > cv) == up){ skey[e] = cv; skey[pr] = av; }
                }
            }
            __syncthreads();
        }
    }
    u64 thr = (r > 0) ? skey[2048 - r] : ~0ull;
    bool none = (r == 0);
    {
        const int p0 = tid*4;
        win[p0+0] = (!none && s0 && k0 >= thr) ? 1 : 0;
        win[p0+1] = (!none && s1 && k1 >= thr) ? 1 : 0;
        win[p0+2] = (!none && s2 && k2 >= thr) ? 1 : 0;
        win[p0+3] = (!none && s3 && k3 >= thr) ? 1 : 0;
    }
    __syncthreads();

    // keep mask + block-wide exclusive scan (4 tokens / thread)
    const int i0 = tid * 4;
    int kf[4]; int lsum = 0;
    #pragma unroll
    for (int c = 0; c < 4; c++){
        int i = i0 + c;
        int kp = (i == 0) ? 1 : (win[i-1] ? 0 : 1);
        kf[c] = kp; lsum += kp;
    }
    int lane = tid & 31, wid = tid >> 5;
    int incl = lsum;
    #pragma unroll
    for (int o = 1; o < 32; o <<= 1){
        int v = __shfl_up_sync(0xffffffffu, incl, o);
        if (lane >= o) incl += v;
    }
    if (lane == 31) ibuf[wid] = incl;
    __syncthreads();
    if (tid < 32){
        int v = ibuf[tid];
        int inc2 = v;
        #pragma unroll
        for (int o = 1; o < 32; o <<= 1){
            int t2 = __shfl_up_sync(0xffffffffu, inc2, o);
            if (tid >= o) inc2 += t2;
        }
        ibuf[tid] = inc2 - v;
    }
    __syncthreads();
    int pos = ibuf[wid] + (incl - lsum);

    const size_t posBase  = (size_t)Bq * s_out * (Dq + NOq);
    const size_t spanBase = posBase + (size_t)Bq * s_out;
    #pragma unroll
    for (int c = 0; c < 4; c++){
        int i = i0 + c;
        if (kf[c]){
            if (pos < s_out){
                int sel = (i < SM1q && win[i]) ? 1 : 0;
                g_idxsel[b*Sq + pos] = (i << 1) | sel;
                out[posBase  + (size_t)b*s_out + pos] = (float)pos_ids[b*Sq + i];
                int sp = span_ids[b*Sq + i] + (sel ? span_ids[b*Sq + i + 1] : 0);
                out[spanBase + (size_t)b*s_out + pos] = (float)sp;
            }
            pos++;
        }
    }
}

// ---------------- K3: gather + weighted merge (the bandwidth kernel) --------
__global__ void __launch_bounds__(256) k_gather(const float* __restrict__ x,
                                                const float* __restrict__ src,
                                                const int* __restrict__ r_in,
                                                float* __restrict__ out){
    int r = r_in ? r_in[0] : 1024;
    if (r < 0) r = 0;
    if (r > Sq/2) r = Sq/2;
    const int s_out = Sq - r;
    const int b = blockIdx.x / Sq;
    const int j = blockIdx.x - b*Sq;
    if (j >= s_out) return;

    const int packed = g_idxsel[b*Sq + j];
    const int i   = packed >> 1;
    const int sel = packed & 1;
    const size_t tin  = (size_t)b*Sq + i;
    const size_t tout = (size_t)b*s_out + j;

    const float4* x0 = (const float4*)(x + tin*Dq);
    float4* xo = (float4*)(out + tout*Dq);
    const float4* s0 = (const float4*)(src + tin*NOq);
    float4* so = (float4*)(out + (size_t)Bq*s_out*Dq + tout*NOq);

    if (sel){
        const float wi = g_gn[tin], wj = g_gn[tin+1];
        const float inv = 1.f / (wi + wj + 1e-8f);
        const float4* x1 = (const float4*)(x + (tin+1)*Dq);
        for (int t = threadIdx.x; t < Dq/4; t += 256){
            float4 a = x0[t], c = x1[t], o;
            o.x = (wi*a.x + wj*c.x)*inv; o.y = (wi*a.y + wj*c.y)*inv;
            o.z = (wi*a.z + wj*c.z)*inv; o.w = (wi*a.w + wj*c.w)*inv;
            xo[t] = o;
        }
        const float4* s1 = (const float4*)(src + (tin+1)*NOq);
        for (int t = threadIdx.x; t < NOq/4; t += 256){
            float4 a = s0[t], c = s1[t], o;
            o.x = a.x+c.x; o.y = a.y+c.y; o.z = a.z+c.z; o.w = a.w+c.w;
            so[t] = o;
        }
    } else {
        for (int t = threadIdx.x; t < Dq/4;  t += 256) xo[t] = x0[t];
        for (int t = threadIdx.x; t < NOq/4; t += 256) so[t] = s0[t];
    }
}

// ---------------- launch ----------------------------------------------------
extern "C" void kernel_launch(void* const* d_in, const int* in_sizes, int n_in,
                              void* d_out, int out_size){
    (void)in_sizes; (void)out_size;
    const float* x    = (const float*)d_in[0];
    const float* src  = (const float*)d_in[1];
    const int*   pos  = (const int*)d_in[2];
    const int*   span = (const int*)d_in[3];
    const float* W    = (const float*)d_in[4];
    const int*   r    = (n_in >= 6) ? (const int*)d_in[5] : nullptr;
    float* out = (float*)d_out;

    k_gemm  <<<256, 256, GEMM_SMEM>>>(x, W);
    k_sim   <<<2048, 256>>>();
    k_select<<<Bq, 1024, SEL_SMEM>>>(pos, span, r, out);
    k_gather<<<Bq*Sq, 256>>>(x, src, r, out);
}

// round 11
// speedup vs baseline: 2.1581x; 1.0671x over previous
#include <cuda_runtime.h>
#include <cuda_bf16.h>
#include <cstdint>

#define Bq 4
#define Sq 4096
#define Dq 768
#define GDq 64
#define NOq 4096
#define SM1q (Sq-1)
#define ROWSq (Bq*Sq)

typedef unsigned long long u64;
typedef unsigned int u32;
typedef unsigned short u16;

// ---------------- scratch (device globals: no allocations allowed) ----------
__device__ float g_gunit[ROWSq*GDq];   // 4 MB  unit-normalized projections
__device__ float g_gn[ROWSq];          // norms
__device__ float g_sim[Bq*SM1q];       // adjacent cosine sims
__device__ int   g_idxsel[ROWSq];      // per output slot: (src_index<<1)|sel

// ---------------- K0: g = x @ W^T via mma.sync bf16 (3-way split, 6 terms) --
// 128 CTAs x 256 thr (8 warps); CTA = 128 rows x 64 gd; K chunked by 128.
// Per chunk: convert x/W fp32 -> 3 bf16 tiles each (hi/mid/lo, swizzled),
// then per k16-step ldmatrix all fragments and issue 6 split-combos x 8 n-tiles
// HMMA into fp32 accumulators. Dropped terms (ml, lm, ll) are <= ~3e-8 rel.
#define OFF_AH 0
#define OFF_AM 32768
#define OFF_AL 65536
#define OFF_BH 98304
#define OFF_BM 114688
#define OFF_BL 131072
#define TC_SMEM 147456

__device__ __forceinline__ u32 smem_u32(const void* p){
    u32 a;
    asm("{ .reg .u64 t; cvta.to.shared.u64 t, %1; cvt.u32.u64 %0, t; }"
        : "=r"(a) : "l"(p));
    return a;
}

// row stride 256B (128 bf16). 16B-unit swizzle: unit ^= (row & 7)
__device__ __forceinline__ u32 tswz(int row, int kbyte){
    return (u32)(row*256 + ((((kbyte >> 4) ^ (row & 7))) << 4) + (kbyte & 15));
}

__device__ __forceinline__ void split3(float v, u16& h, u16& m, u16& l){
    __nv_bfloat16 bh = __float2bfloat16(v);
    float r1 = v - __bfloat162float(bh);
    __nv_bfloat16 bm = __float2bfloat16(r1);
    float r2 = r1 - __bfloat162float(bm);
    __nv_bfloat16 bl = __float2bfloat16(r2);
    h = __bfloat16_as_ushort(bh);
    m = __bfloat16_as_ushort(bm);
    l = __bfloat16_as_ushort(bl);
}

#define LDSM_X4(r0,r1,r2,r3,addr) \
    asm volatile("ldmatrix.sync.aligned.m8n8.x4.shared.b16 {%0,%1,%2,%3}, [%4];" \
        : "=r"(r0), "=r"(r1), "=r"(r2), "=r"(r3) : "r"(addr))

#define HMMA(d, a, b) \
    asm volatile("mma.sync.aligned.m16n8k16.row.col.f32.bf16.bf16.f32 " \
        "{%0,%1,%2,%3}, {%4,%5,%6,%7}, {%8,%9}, {%0,%1,%2,%3};" \
        : "+f"((d)[0]), "+f"((d)[1]), "+f"((d)[2]), "+f"((d)[3]) \
        : "r"((a)[0]), "r"((a)[1]), "r"((a)[2]), "r"((a)[3]), \
          "r"((b)[0]), "r"((b)[1]))

__global__ void __launch_bounds__(256, 1) k_gemm_tc(const float* __restrict__ x,
                                                    const float* __restrict__ W){
    extern __shared__ unsigned char sm[];
    const u32 sb = smem_u32(sm);
    const int tid  = threadIdx.x;
    const int wid  = tid >> 5, lane = tid & 31;
    const int rowBase = blockIdx.x * 128;
    const int m0 = wid * 16;

    float acc[8][4];
    #pragma unroll
    for (int nt = 0; nt < 8; nt++)
        #pragma unroll
        for (int q = 0; q < 4; q++) acc[nt][q] = 0.f;

    const float4* xg = (const float4*)x;
    const float4* Wg = (const float4*)W;

    // precompute per-lane ldmatrix address components
    const int id   = lane >> 3;            // 0..3
    const int l8   = lane & 7;
    const int amr  = m0 + ((id & 1) << 3) + l8;     // A matrix row
    const int akoff = (id >> 1) << 4;               // A k-byte sub-offset
    const int bnr0 = ((id >> 1) << 3) + l8;         // B n row (rel n0)
    const int bkoff = (id & 1) << 4;                // B k-byte sub-offset

    for (int c = 0; c < 6; c++){
        if (c) __syncthreads();            // prev chunk fragments consumed
        // ---- convert x chunk: 128 rows x 32 float4 ; 16 f4/thread ----------
        #pragma unroll
        for (int it = 0; it < 16; it++){
            int f   = tid + it*256;
            int row = f >> 5, k4 = f & 31;
            float4 v = xg[(size_t)(rowBase + row)*192 + c*32 + k4];
            u16 h0,h1,h2,h3, mm0,mm1,mm2,mm3, l0,l1,l2,l3;
            split3(v.x,h0,mm0,l0); split3(v.y,h1,mm1,l1);
            split3(v.z,h2,mm2,l2); split3(v.w,h3,mm3,l3);
            u32 so = tswz(row, k4*8);
            *(uint2*)(sm + OFF_AH + so) =
                make_uint2((u32)h0  | ((u32)h1 <<16), (u32)h2  | ((u32)h3 <<16));
            *(uint2*)(sm + OFF_AM + so) =
                make_uint2((u32)mm0 | ((u32)mm1<<16), (u32)mm2 | ((u32)mm3<<16));
            *(uint2*)(sm + OFF_AL + so) =
                make_uint2((u32)l0  | ((u32)l1 <<16), (u32)l2  | ((u32)l3 <<16));
        }
        // ---- convert W chunk: 64 rows x 32 float4 ; 8 f4/thread ------------
        #pragma unroll
        for (int it = 0; it < 8; it++){
            int f   = tid + it*256;
            int row = f >> 5, k4 = f & 31;
            float4 v = Wg[(size_t)row*192 + c*32 + k4];
            u16 h0,h1,h2,h3, mm0,mm1,mm2,mm3, l0,l1,l2,l3;
            split3(v.x,h0,mm0,l0); split3(v.y,h1,mm1,l1);
            split3(v.z,h2,mm2,l2); split3(v.w,h3,mm3,l3);
            u32 so = tswz(row, k4*8);
            *(uint2*)(sm + OFF_BH + so) =
                make_uint2((u32)h0  | ((u32)h1 <<16), (u32)h2  | ((u32)h3 <<16));
            *(uint2*)(sm + OFF_BM + so) =
                make_uint2((u32)mm0 | ((u32)mm1<<16), (u32)mm2 | ((u32)mm3<<16));
            *(uint2*)(sm + OFF_BL + so) =
                make_uint2((u32)l0  | ((u32)l1 <<16), (u32)l2  | ((u32)l3 <<16));
        }
        __syncthreads();

        #pragma unroll
        for (int ks = 0; ks < 8; ks++){
            const int kb = ks*32;
            u32 A[3][4];
            {
                u32 ao = tswz(amr, kb + akoff);
                LDSM_X4(A[0][0],A[0][1],A[0][2],A[0][3], sb + OFF_AH + ao);
                LDSM_X4(A[1][0],A[1][1],A[1][2],A[1][3], sb + OFF_AM + ao);
                LDSM_X4(A[2][0],A[2][1],A[2][2],A[2][3], sb + OFF_AL + ao);
            }
            u32 Bf[3][8][2];
            #pragma unroll
            for (int np = 0; np < 4; np++){        // n0 = np*16, covers 2 n-tiles
                u32 bo = tswz(np*16 + bnr0, kb + bkoff);
                u32 r0,r1,r2,r3;
                LDSM_X4(r0,r1,r2,r3, sb + OFF_BH + bo);
                Bf[0][np*2][0]=r0; Bf[0][np*2][1]=r1;
                Bf[0][np*2+1][0]=r2; Bf[0][np*2+1][1]=r3;
                LDSM_X4(r0,r1,r2,r3, sb + OFF_BM + bo);
                Bf[1][np*2][0]=r0; Bf[1][np*2][1]=r1;
                Bf[1][np*2+1][0]=r2; Bf[1][np*2+1][1]=r3;
                LDSM_X4(r0,r1,r2,r3, sb + OFF_BL + bo);
                Bf[2][np*2][0]=r0; Bf[2][np*2][1]=r1;
                Bf[2][np*2+1][0]=r2; Bf[2][np*2+1][1]=r3;
            }
            // 6 significant split combos: hh, hm, mh, hl, lh, mm
            #pragma unroll
            for (int nt = 0; nt < 8; nt++) HMMA(acc[nt], A[0], Bf[0][nt]);
            #pragma unroll
            for (int nt = 0; nt < 8; nt++) HMMA(acc[nt], A[0], Bf[1][nt]);
            #pragma unroll
            for (int nt = 0; nt < 8; nt++) HMMA(acc[nt], A[1], Bf[0][nt]);
            #pragma unroll
            for (int nt = 0; nt < 8; nt++) HMMA(acc[nt], A[0], Bf[2][nt]);
            #pragma unroll
            for (int nt = 0; nt < 8; nt++) HMMA(acc[nt], A[2], Bf[0][nt]);
            #pragma unroll
            for (int nt = 0; nt < 8; nt++) HMMA(acc[nt], A[1], Bf[1][nt]);
        }
    }

    // ---- epilogue: norms + normalized g_unit straight from fragments -------
    // lane holds rows r1 = m0 + lane/4 (regs 0,1) and r2 = r1+8 (regs 2,3),
    // cols nt*8 + (lane&3)*2 + {0,1}.
    {
        const int qr = lane >> 2;          // 0..7
        const int qc = lane & 3;           // quad col group
        const int r1 = rowBase + m0 + qr;
        const int r2 = r1 + 8;

        float s1 = 0.f, s2 = 0.f;
        #pragma unroll
        for (int nt = 0; nt < 8; nt++){
            s1 = fmaf(acc[nt][0], acc[nt][0], s1);
            s1 = fmaf(acc[nt][1], acc[nt][1], s1);
            s2 = fmaf(acc[nt][2], acc[nt][2], s2);
            s2 = fmaf(acc[nt][3], acc[nt][3], s2);
        }
        // reduce across the 4 lanes of the quad (fixed order: xor 1 then 2)
        s1 += __shfl_xor_sync(0xffffffffu, s1, 1);
        s1 += __shfl_xor_sync(0xffffffffu, s1, 2);
        s2 += __shfl_xor_sync(0xffffffffu, s2, 1);
        s2 += __shfl_xor_sync(0xffffffffu, s2, 2);

        float n1 = __fsqrt_rn(s1), n2 = __fsqrt_rn(s2);
        if (qc == 0){ g_gn[r1] = n1; g_gn[r2] = n2; }
        float d1 = fmaxf(n1, 1e-12f), d2 = fmaxf(n2, 1e-12f);

        float2* go = (float2*)g_gunit;
        #pragma unroll
        for (int nt = 0; nt < 8; nt++){
            float2 o1, o2;
            o1.x = __fdiv_rn(acc[nt][0], d1);
            o1.y = __fdiv_rn(acc[nt][1], d1);
            o2.x = __fdiv_rn(acc[nt][2], d2);
            o2.y = __fdiv_rn(acc[nt][3], d2);
            go[(size_t)r1*32 + nt*4 + qc] = o1;
            go[(size_t)r2*32 + nt*4 + qc] = o2;
        }
    }
}

// ---------------- K1: sim = dot(g_unit[s], g_unit[s+1]) ---------------------
__global__ void __launch_bounds__(256) k_sim(){
    int warp = (blockIdx.x * blockDim.x + threadIdx.x) >> 5;
    int lane = threadIdx.x & 31;
    if (warp >= Bq*SM1q) return;
    int b = warp / SM1q, s = warp % SM1q;
    const float* a = g_gunit + ((size_t)(b*Sq + s))*GDq;
    float v = fmaf(a[lane], a[lane + GDq], a[lane+32]*a[lane+32+GDq]);
    #pragma unroll
    for (int o=16;o;o>>=1) v += __shfl_xor_sync(0xffffffffu, v, o);
    if (!lane) g_sim[warp] = v;
}

// ---------------- K2: greedy matching + cap + compaction --------------------
#define SEL_SMEM 24832
__global__ void __launch_bounds__(1024) k_select(const int* __restrict__ pos_ids,
                                                 const int* __restrict__ span_ids,
                                                 const int* __restrict__ r_in,
                                                 float* __restrict__ out){
    extern __shared__ unsigned char smraw[];
    u64* ek0 = (u64*)smraw;
    u64* ek3 = (u64*)(smraw + 8192);
    u64* skey = (u64*)smraw;
    unsigned char* ea0 = smraw + 16384;
    unsigned char* ea3 = smraw + 17408;
    unsigned char* ew0 = smraw + 18432;
    unsigned char* ew3 = smraw + 19456;
    unsigned char* win = smraw + 20480;
    int* ibuf     = (int*)(smraw + 24576);
    int* counters = (int*)(smraw + 24704);

    const int tid = threadIdx.x;
    const int b   = blockIdx.x;
    int r = r_in ? r_in[0] : 1024;
    if (r < 0) r = 0;
    if (r > Sq/2) r = Sq/2;
    const int s_out = Sq - r;

    u64 k0,k1,k2,k3;
    bool a0,a1,a2,a3;
    {
        const int p0 = tid*4;
        float4 sv;
        sv.x = (p0+0 < SM1q) ? g_sim[b*SM1q + p0+0] : 0.f;
        sv.y = (p0+1 < SM1q) ? g_sim[b*SM1q + p0+1] : 0.f;
        sv.z = (p0+2 < SM1q) ? g_sim[b*SM1q + p0+2] : 0.f;
        sv.w = (p0+3 < SM1q) ? g_sim[b*SM1q + p0+3] : 0.f;
        u32 u;
        u = __float_as_uint(sv.x); u = (u & 0x80000000u) ? ~u : (u | 0x80000000u);
        k0 = ((u64)u << 32) | (u32)(0xFFFFFFFFu - (u32)(p0+0));
        u = __float_as_uint(sv.y); u = (u & 0x80000000u) ? ~u : (u | 0x80000000u);
        k1 = ((u64)u << 32) | (u32)(0xFFFFFFFFu - (u32)(p0+1));
        u = __float_as_uint(sv.z); u = (u & 0x80000000u) ? ~u : (u | 0x80000000u);
        k2 = ((u64)u << 32) | (u32)(0xFFFFFFFFu - (u32)(p0+2));
        u = __float_as_uint(sv.w); u = (u & 0x80000000u) ? ~u : (u | 0x80000000u);
        k3 = ((u64)u << 32) | (u32)(0xFFFFFFFFu - (u32)(p0+3));
        a0 = (p0+0 < SM1q); a1 = (p0+1 < SM1q);
        a2 = (p0+2 < SM1q); a3 = (p0+3 < SM1q);
        if (!a3) k3 = 0ull;
    }
    bool s0=false, s1=false, s2=false, s3=false;
    if (tid == 0) counters[0] = 0;

    while (true){
        ek0[tid] = k0; ea0[tid] = a0;
        ek3[tid] = k3; ea3[tid] = a3;
        __syncthreads();
        u64 lk = 0, rk = 0; bool la = false, ra = false;
        if (tid > 0)    { lk = ek3[tid-1]; la = ea3[tid-1] != 0; }
        if (tid < 1023) { rk = ek0[tid+1]; ra = ea0[tid+1] != 0; }

        bool w0 = a0 && !(la && lk > k0) && !(a1 && k1 > k0);
        bool w1 = a1 && !(a0 && k0 > k1) && !(a2 && k2 > k1);
        bool w2 = a2 && !(a1 && k1 > k2) && !(a3 && k3 > k2);
        bool w3 = a3 && !(a2 && k2 > k3) && !(ra && rk > k3);

        ew0[tid] = w0; ew3[tid] = w3;
        __syncthreads();
        bool lw = (tid > 0)    ? (ew3[tid-1] != 0) : false;
        bool rw = (tid < 1023) ? (ew0[tid+1] != 0) : false;

        s0 |= w0; s1 |= w1; s2 |= w2; s3 |= w3;
        a0 = a0 && !w0 && !lw && !w1;
        a1 = a1 && !w1 && !w0 && !w2;
        a2 = a2 && !w2 && !w1 && !w3;
        a3 = a3 && !w3 && !w2 && !rw;

        int cont = __syncthreads_or((int)(a0|a1|a2|a3));
        if (!cont) break;
    }

    __syncthreads();
    {
        if (s0){ int i2 = atomicAdd(counters, 1); skey[i2] = k0; }
        if (s1){ int i2 = atomicAdd(counters, 1); skey[i2] = k1; }
        if (s2){ int i2 = atomicAdd(counters, 1); skey[i2] = k2; }
        if (s3){ int i2 = atomicAdd(counters, 1); skey[i2] = k3; }
    }
    __syncthreads();
    int M = counters[0];
    for (int e = tid; e < 2048; e += 1024) if (e >= M) skey[e] = 0ull;
    __syncthreads();
    for (int kk = 2; kk <= 2048; kk <<= 1){
        for (int j = kk >> 1; j > 0; j >>= 1){
            for (int e = tid; e < 2048; e += 1024){
                int pr = e ^ j;
                if (pr > e){
                    bool up = ((e & kk) == 0);
                    u64 av = skey[e], cv = skey[pr];
                    if ((av > cv) == up){ skey[e] = cv; skey[pr] = av; }
                }
            }
            __syncthreads();
        }
    }
    u64 thr = (r > 0) ? skey[2048 - r] : ~0ull;
    bool none = (r == 0);
    {
        const int p0 = tid*4;
        win[p0+0] = (!none && s0 && k0 >= thr) ? 1 : 0;
        win[p0+1] = (!none && s1 && k1 >= thr) ? 1 : 0;
        win[p0+2] = (!none && s2 && k2 >= thr) ? 1 : 0;
        win[p0+3] = (!none && s3 && k3 >= thr) ? 1 : 0;
    }
    __syncthreads();

    const int i0 = tid * 4;
    int kf[4]; int lsum = 0;
    #pragma unroll
    for (int c = 0; c < 4; c++){
        int i = i0 + c;
        int kp = (i == 0) ? 1 : (win[i-1] ? 0 : 1);
        kf[c] = kp; lsum += kp;
    }
    int lane = tid & 31, wid = tid >> 5;
    int incl = lsum;
    #pragma unroll
    for (int o = 1; o < 32; o <<= 1){
        int v = __shfl_up_sync(0xffffffffu, incl, o);
        if (lane >= o) incl += v;
    }
    if (lane == 31) ibuf[wid] = incl;
    __syncthreads();
    if (tid < 32){
        int v = ibuf[tid];
        int inc2 = v;
        #pragma unroll
        for (int o = 1; o < 32; o <<= 1){
            int t2 = __shfl_up_sync(0xffffffffu, inc2, o);
            if (tid >= o) inc2 += t2;
        }
        ibuf[tid] = inc2 - v;
    }
    __syncthreads();
    int pos = ibuf[wid] + (incl - lsum);

    const size_t posBase  = (size_t)Bq * s_out * (Dq + NOq);
    const size_t spanBase = posBase + (size_t)Bq * s_out;
    #pragma unroll
    for (int c = 0; c < 4; c++){
        int i = i0 + c;
        if (kf[c]){
            if (pos < s_out){
                int sel = (i < SM1q && win[i]) ? 1 : 0;
                g_idxsel[b*Sq + pos] = (i << 1) | sel;
                out[posBase  + (size_t)b*s_out + pos] = (float)pos_ids[b*Sq + i];
                int sp = span_ids[b*Sq + i] + (sel ? span_ids[b*Sq + i + 1] : 0);
                out[spanBase + (size_t)b*s_out + pos] = (float)sp;
            }
            pos++;
        }
    }
}

// ---------------- K3: gather + weighted merge (the bandwidth kernel) --------
__global__ void __launch_bounds__(256) k_gather(const float* __restrict__ x,
                                                const float* __restrict__ src,
                                                const int* __restrict__ r_in,
                                                float* __restrict__ out){
    int r = r_in ? r_in[0] : 1024;
    if (r < 0) r = 0;
    if (r > Sq/2) r = Sq/2;
    const int s_out = Sq - r;
    const int b = blockIdx.x / Sq;
    const int j = blockIdx.x - b*Sq;
    if (j >= s_out) return;

    const int packed = g_idxsel[b*Sq + j];
    const int i   = packed >> 1;
    const int sel = packed & 1;
    const size_t tin  = (size_t)b*Sq + i;
    const size_t tout = (size_t)b*s_out + j;

    const float4* x0 = (const float4*)(x + tin*Dq);
    float4* xo = (float4*)(out + tout*Dq);
    const float4* s0 = (const float4*)(src + tin*NOq);
    float4* so = (float4*)(out + (size_t)Bq*s_out*Dq + tout*NOq);

    if (sel){
        const float wi = g_gn[tin], wj = g_gn[tin+1];
        const float inv = 1.f / (wi + wj + 1e-8f);
        const float4* x1 = (const float4*)(x + (tin+1)*Dq);
        for (int t = threadIdx.x; t < Dq/4; t += 256){
            float4 a = x0[t], c = x1[t], o;
            o.x = (wi*a.x + wj*c.x)*inv; o.y = (wi*a.y + wj*c.y)*inv;
            o.z = (wi*a.z + wj*c.z)*inv; o.w = (wi*a.w + wj*c.w)*inv;
            xo[t] = o;
        }
        const float4* s1 = (const float4*)(src + (tin+1)*NOq);
        for (int t = threadIdx.x; t < NOq/4; t += 256){
            float4 a = s0[t], c = s1[t], o;
            o.x = a.x+c.x; o.y = a.y+c.y; o.z = a.z+c.z; o.w = a.w+c.w;
            so[t] = o;
        }
    } else {
        for (int t = threadIdx.x; t < Dq/4;  t += 256) xo[t] = x0[t];
        for (int t = threadIdx.x; t < NOq/4; t += 256) so[t] = s0[t];
    }
}

// ---------------- launch ----------------------------------------------------
extern "C" void kernel_launch(void* const* d_in, const int* in_sizes, int n_in,
                              void* d_out, int out_size){
    (void)in_sizes; (void)out_size;
    const float* x    = (const float*)d_in[0];
    const float* src  = (const float*)d_in[1];
    const int*   pos  = (const int*)d_in[2];
    const int*   span = (const int*)d_in[3];
    const float* W    = (const float*)d_in[4];
    const int*   r    = (n_in >= 6) ? (const int*)d_in[5] : nullptr;
    float* out = (float*)d_out;

    cudaFuncSetAttribute(k_gemm_tc, cudaFuncAttributeMaxDynamicSharedMemorySize, TC_SMEM);

    k_gemm_tc<<<128, 256, TC_SMEM>>>(x, W);
    k_sim    <<<2048, 256>>>();
    k_select <<<Bq, 1024, SEL_SMEM>>>(pos, span, r, out);
    k_gather <<<Bq*Sq, 256>>>(x, src, r, out);
}

// round 13
// speedup vs baseline: 2.3142x; 1.0723x over previous
#include <cuda_runtime.h>
#include <cuda_bf16.h>
#include <cstdint>

#define Bq 4
#define Sq 4096
#define Dq 768
#define GDq 64
#define NOq 4096
#define SM1q (Sq-1)
#define ROWSq (Bq*Sq)

typedef unsigned long long u64;
typedef unsigned int u32;
typedef unsigned short u16;

// ---------------- scratch (device globals: no allocations allowed) ----------
__device__ float g_gn[ROWSq];          // norms
__device__ float g_sim[Bq*SM1q];       // adjacent cosine sims
__device__ int   g_idxsel[ROWSq];      // per output slot: (src_index<<1)|sel
__device__ float g_brow0[128*64];      // normalized row 0 of each CTA
__device__ float g_brow1[128*64];      // normalized row 127 of each CTA

// ---------------- K0: g = x @ W^T via mma.sync bf16 (3-way split, 6 terms) --
// 128 CTAs x 256 thr (8 warps); CTA = 128 rows x 64 gd; K chunked by 128.
// Epilogue: normalized rows -> smem, in-CTA adjacent sims computed here with
// the exact k_sim reduction order; boundary rows exported for k_bsim.
#define OFF_AH 0
#define OFF_AM 32768
#define OFF_AL 65536
#define OFF_BH 98304
#define OFF_BM 114688
#define OFF_BL 131072
#define TC_SMEM 147456

__device__ __forceinline__ u32 smem_u32(const void* p){
    u32 a;
    asm("{ .reg .u64 t; cvta.to.shared.u64 t, %1; cvt.u32.u64 %0, t; }"
        : "=r"(a) : "l"(p));
    return a;
}

// row stride 256B (128 bf16). 16B-unit swizzle: unit ^= (row & 7)
__device__ __forceinline__ u32 tswz(int row, int kbyte){
    return (u32)(row*256 + ((((kbyte >> 4) ^ (row & 7))) << 4) + (kbyte & 15));
}

__device__ __forceinline__ void split3(float v, u16& h, u16& m, u16& l){
    __nv_bfloat16 bh = __float2bfloat16(v);
    float r1 = v - __bfloat162float(bh);
    __nv_bfloat16 bm = __float2bfloat16(r1);
    float r2 = r1 - __bfloat162float(bm);
    __nv_bfloat16 bl = __float2bfloat16(r2);
    h = __bfloat16_as_ushort(bh);
    m = __bfloat16_as_ushort(bm);
    l = __bfloat16_as_ushort(bl);
}

#define LDSM_X4(r0,r1,r2,r3,addr) \
    asm volatile("ldmatrix.sync.aligned.m8n8.x4.shared.b16 {%0,%1,%2,%3}, [%4];" \
        : "=r"(r0), "=r"(r1), "=r"(r2), "=r"(r3) : "r"(addr))

#define HMMA(d, a, b) \
    asm volatile("mma.sync.aligned.m16n8k16.row.col.f32.bf16.bf16.f32 " \
        "{%0,%1,%2,%3}, {%4,%5,%6,%7}, {%8,%9}, {%0,%1,%2,%3};" \
        : "+f"((d)[0]), "+f"((d)[1]), "+f"((d)[2]), "+f"((d)[3]) \
        : "r"((a)[0]), "r"((a)[1]), "r"((a)[2]), "r"((a)[3]), \
          "r"((b)[0]), "r"((b)[1]))

__global__ void __launch_bounds__(256, 1) k_gemm_tc(const float* __restrict__ x,
                                                    const float* __restrict__ W){
    extern __shared__ unsigned char sm[];
    const u32 sb = smem_u32(sm);
    const int tid  = threadIdx.x;
    const int wid  = tid >> 5, lane = tid & 31;
    const int rowBase = blockIdx.x * 128;
    const int m0 = wid * 16;

    float acc[8][4];
    #pragma unroll
    for (int nt = 0; nt < 8; nt++)
        #pragma unroll
        for (int q = 0; q < 4; q++) acc[nt][q] = 0.f;

    const float4* xg = (const float4*)x;
    const float4* Wg = (const float4*)W;

    const int id   = lane >> 3;
    const int l8   = lane & 7;
    const int amr  = m0 + ((id & 1) << 3) + l8;
    const int akoff = (id >> 1) << 4;
    const int bnr0 = ((id >> 1) << 3) + l8;
    const int bkoff = (id & 1) << 4;

    for (int c = 0; c < 6; c++){
        if (c) __syncthreads();
        #pragma unroll
        for (int it = 0; it < 16; it++){
            int f   = tid + it*256;
            int row = f >> 5, k4 = f & 31;
            float4 v = xg[(size_t)(rowBase + row)*192 + c*32 + k4];
            u16 h0,h1,h2,h3, mm0,mm1,mm2,mm3, l0,l1,l2,l3;
            split3(v.x,h0,mm0,l0); split3(v.y,h1,mm1,l1);
            split3(v.z,h2,mm2,l2); split3(v.w,h3,mm3,l3);
            u32 so = tswz(row, k4*8);
            *(uint2*)(sm + OFF_AH + so) =
                make_uint2((u32)h0  | ((u32)h1 <<16), (u32)h2  | ((u32)h3 <<16));
            *(uint2*)(sm + OFF_AM + so) =
                make_uint2((u32)mm0 | ((u32)mm1<<16), (u32)mm2 | ((u32)mm3<<16));
            *(uint2*)(sm + OFF_AL + so) =
                make_uint2((u32)l0  | ((u32)l1 <<16), (u32)l2  | ((u32)l3 <<16));
        }
        #pragma unroll
        for (int it = 0; it < 8; it++){
            int f   = tid + it*256;
            int row = f >> 5, k4 = f & 31;
            float4 v = Wg[(size_t)row*192 + c*32 + k4];
            u16 h0,h1,h2,h3, mm0,mm1,mm2,mm3, l0,l1,l2,l3;
            split3(v.x,h0,mm0,l0); split3(v.y,h1,mm1,l1);
            split3(v.z,h2,mm2,l2); split3(v.w,h3,mm3,l3);
            u32 so = tswz(row, k4*8);
            *(uint2*)(sm + OFF_BH + so) =
                make_uint2((u32)h0  | ((u32)h1 <<16), (u32)h2  | ((u32)h3 <<16));
            *(uint2*)(sm + OFF_BM + so) =
                make_uint2((u32)mm0 | ((u32)mm1<<16), (u32)mm2 | ((u32)mm3<<16));
            *(uint2*)(sm + OFF_BL + so) =
                make_uint2((u32)l0  | ((u32)l1 <<16), (u32)l2  | ((u32)l3 <<16));
        }
        __syncthreads();

        #pragma unroll
        for (int ks = 0; ks < 8; ks++){
            const int kb = ks*32;
            u32 A[3][4];
            {
                u32 ao = tswz(amr, kb + akoff);
                LDSM_X4(A[0][0],A[0][1],A[0][2],A[0][3], sb + OFF_AH + ao);
                LDSM_X4(A[1][0],A[1][1],A[1][2],A[1][3], sb + OFF_AM + ao);
                LDSM_X4(A[2][0],A[2][1],A[2][2],A[2][3], sb + OFF_AL + ao);
            }
            u32 Bf[3][8][2];
            #pragma unroll
            for (int np = 0; np < 4; np++){
                u32 bo = tswz(np*16 + bnr0, kb + bkoff);
                u32 r0,r1,r2,r3;
                LDSM_X4(r0,r1,r2,r3, sb + OFF_BH + bo);
                Bf[0][np*2][0]=r0; Bf[0][np*2][1]=r1;
                Bf[0][np*2+1][0]=r2; Bf[0][np*2+1][1]=r3;
                LDSM_X4(r0,r1,r2,r3, sb + OFF_BM + bo);
                Bf[1][np*2][0]=r0; Bf[1][np*2][1]=r1;
                Bf[1][np*2+1][0]=r2; Bf[1][np*2+1][1]=r3;
                LDSM_X4(r0,r1,r2,r3, sb + OFF_BL + bo);
                Bf[2][np*2][0]=r0; Bf[2][np*2][1]=r1;
                Bf[2][np*2+1][0]=r2; Bf[2][np*2+1][1]=r3;
            }
            #pragma unroll
            for (int nt = 0; nt < 8; nt++) HMMA(acc[nt], A[0], Bf[0][nt]);
            #pragma unroll
            for (int nt = 0; nt < 8; nt++) HMMA(acc[nt], A[0], Bf[1][nt]);
            #pragma unroll
            for (int nt = 0; nt < 8; nt++) HMMA(acc[nt], A[1], Bf[0][nt]);
            #pragma unroll
            for (int nt = 0; nt < 8; nt++) HMMA(acc[nt], A[0], Bf[2][nt]);
            #pragma unroll
            for (int nt = 0; nt < 8; nt++) HMMA(acc[nt], A[2], Bf[0][nt]);
            #pragma unroll
            for (int nt = 0; nt < 8; nt++) HMMA(acc[nt], A[1], Bf[1][nt]);
        }
    }

    // ---- epilogue: norms; normalized rows -> smem; in-CTA sims -------------
    __syncthreads();                       // all smem tile reads done
    float* gu = (float*)sm;                // [128][64] normalized rows (32 KB)
    {
        const int qr = lane >> 2;
        const int qc = lane & 3;
        const int r1l = m0 + qr;
        const int r2l = r1l + 8;

        float s1 = 0.f, s2 = 0.f;
        #pragma unroll
        for (int nt = 0; nt < 8; nt++){
            s1 = fmaf(acc[nt][0], acc[nt][0], s1);
            s1 = fmaf(acc[nt][1], acc[nt][1], s1);
            s2 = fmaf(acc[nt][2], acc[nt][2], s2);
            s2 = fmaf(acc[nt][3], acc[nt][3], s2);
        }
        s1 += __shfl_xor_sync(0xffffffffu, s1, 1);
        s1 += __shfl_xor_sync(0xffffffffu, s1, 2);
        s2 += __shfl_xor_sync(0xffffffffu, s2, 1);
        s2 += __shfl_xor_sync(0xffffffffu, s2, 2);

        float n1 = __fsqrt_rn(s1), n2 = __fsqrt_rn(s2);
        if (qc == 0){ g_gn[rowBase + r1l] = n1; g_gn[rowBase + r2l] = n2; }
        float d1 = fmaxf(n1, 1e-12f), d2 = fmaxf(n2, 1e-12f);

        #pragma unroll
        for (int nt = 0; nt < 8; nt++){
            float2 o1, o2;
            o1.x = __fdiv_rn(acc[nt][0], d1);
            o1.y = __fdiv_rn(acc[nt][1], d1);
            o2.x = __fdiv_rn(acc[nt][2], d2);
            o2.y = __fdiv_rn(acc[nt][3], d2);
            *(float2*)(gu + r1l*64 + nt*8 + qc*2) = o1;
            *(float2*)(gu + r2l*64 + nt*8 + qc*2) = o2;
        }
    }
    __syncthreads();

    // in-CTA adjacent sims: identical reduction order to the old k_sim
    {
        const int bIdx = rowBase >> 12;
        const int s0   = rowBase & 4095;
        for (int j = wid; j < 127; j += 8){
            const float* A  = gu + j*64;
            const float* Bv = gu + (j+1)*64;
            float v = fmaf(A[lane], Bv[lane], A[lane+32]*Bv[lane+32]);
            #pragma unroll
            for (int o = 16; o; o >>= 1) v += __shfl_xor_sync(0xffffffffu, v, o);
            if (!lane) g_sim[bIdx*SM1q + s0 + j] = v;
        }
    }
    // export boundary rows for k_bsim
    if (tid < 64)       g_brow0[blockIdx.x*64 + tid]        = gu[tid];
    else if (tid < 128) g_brow1[blockIdx.x*64 + (tid - 64)] = gu[127*64 + tid - 64];
}

// ---------------- K1: boundary sims (CTA row127 <-> next CTA row0) ----------
__global__ void __launch_bounds__(992) k_bsim(){
    const int w = threadIdx.x >> 5;        // 0..30
    const int lane = threadIdx.x & 31;
    const int b = blockIdx.x;
    const int c = b*32 + w;
    const float* A  = g_brow1 + c*64;
    const float* Bv = g_brow0 + (c+1)*64;
    float v = fmaf(A[lane], Bv[lane], A[lane+32]*Bv[lane+32]);
    #pragma unroll
    for (int o = 16; o; o >>= 1) v += __shfl_xor_sync(0xffffffffu, v, o);
    if (!lane) g_sim[b*SM1q + w*128 + 127] = v;
}

// ---------------- K2: greedy matching + cap + compaction --------------------
// Keys in registers; per matching round publish ONLY a 4-bit alive byte
// (2 barriers/round). Threshold via exact 64-bit radix select (8 levels).
#define SEL_SMEM 39168
__global__ void __launch_bounds__(1024) k_select(const int* __restrict__ pos_ids,
                                                 const int* __restrict__ span_ids,
                                                 const int* __restrict__ r_in,
                                                 float* __restrict__ out){
    extern __shared__ unsigned char smraw[];
    u64* key  = (u64*)smraw;                       // [4096]  32768 B
    unsigned char* ab  = smraw + 32768;            // [1024] alive bytes
    unsigned char* win = smraw + 33792;            // [4096] final selection
    int* hist = (int*)(smraw + 37888);             // [256]
    int* ibuf = (int*)(smraw + 38912);             // [32]
    u64* pfx  = (u64*)(smraw + 39040);             // [1]
    int* prnk = (int*)(smraw + 39048);             // [1]

    const int tid = threadIdx.x;
    const int b   = blockIdx.x;
    int r = r_in ? r_in[0] : 1024;
    if (r < 0) r = 0;
    if (r > Sq/2) r = Sq/2;
    const int s_out = Sq - r;
    const int p0 = tid*4;

    // strict-total-order keys: sim desc, index asc
    u64 k0,k1,k2,k3;
    bool a0,a1,a2,a3;
    {
        float4 sv;
        sv.x = (p0+0 < SM1q) ? g_sim[b*SM1q + p0+0] : 0.f;
        sv.y = (p0+1 < SM1q) ? g_sim[b*SM1q + p0+1] : 0.f;
        sv.z = (p0+2 < SM1q) ? g_sim[b*SM1q + p0+2] : 0.f;
        sv.w = (p0+3 < SM1q) ? g_sim[b*SM1q + p0+3] : 0.f;
        u32 u;
        u = __float_as_uint(sv.x); u = (u & 0x80000000u) ? ~u : (u | 0x80000000u);
        k0 = ((u64)u << 32) | (u32)(0xFFFFFFFFu - (u32)(p0+0));
        u = __float_as_uint(sv.y); u = (u & 0x80000000u) ? ~u : (u | 0x80000000u);
        k1 = ((u64)u << 32) | (u32)(0xFFFFFFFFu - (u32)(p0+1));
        u = __float_as_uint(sv.z); u = (u & 0x80000000u) ? ~u : (u | 0x80000000u);
        k2 = ((u64)u << 32) | (u32)(0xFFFFFFFFu - (u32)(p0+2));
        u = __float_as_uint(sv.w); u = (u & 0x80000000u) ? ~u : (u | 0x80000000u);
        k3 = ((u64)u << 32) | (u32)(0xFFFFFFFFu - (u32)(p0+3));
        a0 = (p0+0 < SM1q); a1 = (p0+1 < SM1q);
        a2 = (p0+2 < SM1q); a3 = (p0+3 < SM1q);
        if (!a3) k3 = 0ull;
    }
    // publish keys once; fetch loop-invariant neighbor keys into registers
    key[p0+0] = k0; key[p0+1] = k1; key[p0+2] = k2; key[p0+3] = k3;
    __syncthreads();
    u64 lk2 = 0, lk3 = 0, rk0 = 0, rk1 = 0;
    if (tid > 0)    { lk2 = key[p0-2]; lk3 = key[p0-1]; }
    if (tid < 1023) { rk0 = key[p0+4]; rk1 = key[p0+5]; }

    bool s0=false, s1=false, s2=false, s3=false;

    // iterative local-max matching; only alive bits move through smem
    while (true){
        ab[tid] = (unsigned char)((a0?1:0) | (a1?2:0) | (a2?4:0) | (a3?8:0));
        __syncthreads();
        unsigned char lab = (tid > 0)    ? ab[tid-1] : 0;
        unsigned char rab = (tid < 1023) ? ab[tid+1] : 0;
        bool la2 = lab & 4, la3 = lab & 8;
        bool ra0 = rab & 1, ra1 = rab & 2;

        bool w0 = a0 && !(la3 && lk3 > k0) && !(a1 && k1 > k0);
        bool w1 = a1 && !(a0 && k0 > k1) && !(a2 && k2 > k1);
        bool w2 = a2 && !(a1 && k1 > k2) && !(a3 && k3 > k2);
        bool w3 = a3 && !(a2 && k2 > k3) && !(ra0 && rk0 > k3);
        // neighbors' boundary wins, derived locally by the same rule
        bool lw = la3 && !(la2 && lk2 > lk3) && !(a0 && k0 > lk3);
        bool rw = ra0 && !(a3 && k3 > rk0) && !(ra1 && rk1 > rk0);

        s0 |= w0; s1 |= w1; s2 |= w2; s3 |= w3;
        a0 = a0 && !w0 && !lw && !w1;
        a1 = a1 && !w1 && !w0 && !w2;
        a2 = a2 && !w2 && !w1 && !w3;
        a3 = a3 && !w3 && !w2 && !rw;

        int cont = __syncthreads_or((int)(a0|a1|a2|a3));
        if (!cont) break;
    }

    // exact radix select: thr = r-th largest selected key (keys distinct)
    u64 thr = ~0ull;
    if (r > 0){
        u64 prefix = 0; int rank = r;
        for (int lvl = 7; lvl >= 0; lvl--){
            const int shift = lvl*8;
            if (tid < 256) hist[tid] = 0;
            __syncthreads();
            {
                bool m0_ = s0 && ((lvl == 7) || ((k0 >> (shift+8)) == (prefix >> (shift+8))));
                bool m1_ = s1 && ((lvl == 7) || ((k1 >> (shift+8)) == (prefix >> (shift+8))));
                bool m2_ = s2 && ((lvl == 7) || ((k2 >> (shift+8)) == (prefix >> (shift+8))));
                bool m3_ = s3 && ((lvl == 7) || ((k3 >> (shift+8)) == (prefix >> (shift+8))));
                if (m0_) atomicAdd(&hist[(int)((k0 >> shift) & 255)], 1);
                if (m1_) atomicAdd(&hist[(int)((k1 >> shift) & 255)], 1);
                if (m2_) atomicAdd(&hist[(int)((k2 >> shift) & 255)], 1);
                if (m3_) atomicAdd(&hist[(int)((k3 >> shift) & 255)], 1);
            }
            __syncthreads();
            if (tid < 32){
                const int base = tid*8;
                int h[8]; int T = 0;
                #pragma unroll
                for (int q = 0; q < 8; q++){ h[q] = hist[base+q]; T += h[q]; }
                int S = T;
                #pragma unroll
                for (int o = 1; o < 32; o <<= 1){
                    int v = __shfl_down_sync(0xffffffffu, S, o);
                    if (tid + o < 32) S += v;
                }
                unsigned mask = __ballot_sync(0xffffffffu, S >= rank);
                int owner = 31 - __clz(mask);
                if (tid == owner){
                    int cum = S - T;
                    #pragma unroll
                    for (int q = 7; q >= 0; q--){
                        cum += h[q];
                        if (cum >= rank){
                            pfx[0]  = prefix | ((u64)(u32)(base + q) << shift);
                            prnk[0] = rank - (cum - h[q]);
                            break;
                        }
                    }
                }
            }
            __syncthreads();
            prefix = pfx[0]; rank = prnk[0];
        }
        thr = prefix;
    }

    const bool none = (r == 0);
    win[p0+0] = (!none && s0 && k0 >= thr) ? 1 : 0;
    win[p0+1] = (!none && s1 && k1 >= thr) ? 1 : 0;
    win[p0+2] = (!none && s2 && k2 >= thr) ? 1 : 0;
    win[p0+3] = (!none && s3 && k3 >= thr) ? 1 : 0;
    __syncthreads();

    // keep mask + block-wide exclusive scan (4 tokens / thread)
    const int i0 = tid * 4;
    int kf[4]; int lsum = 0;
    #pragma unroll
    for (int c = 0; c < 4; c++){
        int i = i0 + c;
        int kp = (i == 0) ? 1 : (win[i-1] ? 0 : 1);
        kf[c] = kp; lsum += kp;
    }
    int lane = tid & 31, wid = tid >> 5;
    int incl = lsum;
    #pragma unroll
    for (int o = 1; o < 32; o <<= 1){
        int v = __shfl_up_sync(0xffffffffu, incl, o);
        if (lane >= o) incl += v;
    }
    if (lane == 31) ibuf[wid] = incl;
    __syncthreads();
    if (tid < 32){
        int v = ibuf[tid];
        int inc2 = v;
        #pragma unroll
        for (int o = 1; o < 32; o <<= 1){
            int t2 = __shfl_up_sync(0xffffffffu, inc2, o);
            if (tid >= o) inc2 += t2;
        }
        ibuf[tid] = inc2 - v;
    }
    __syncthreads();
    int pos = ibuf[wid] + (incl - lsum);

    const size_t posBase  = (size_t)Bq * s_out * (Dq + NOq);
    const size_t spanBase = posBase + (size_t)Bq * s_out;
    #pragma unroll
    for (int c = 0; c < 4; c++){
        int i = i0 + c;
        if (kf[c]){
            if (pos < s_out){
                int sel = (i < SM1q && win[i]) ? 1 : 0;
                g_idxsel[b*Sq + pos] = (i << 1) | sel;
                out[posBase  + (size_t)b*s_out + pos] = (float)pos_ids[b*Sq + i];
                int sp = span_ids[b*Sq + i] + (sel ? span_ids[b*Sq + i + 1] : 0);
                out[spanBase + (size_t)b*s_out + pos] = (float)sp;
            }
            pos++;
        }
    }
}

// ---------------- K3: gather + weighted merge (the bandwidth kernel) --------
__global__ void __launch_bounds__(256) k_gather(const float* __restrict__ x,
                                                const float* __restrict__ src,
                                                const int* __restrict__ r_in,
                                                float* __restrict__ out){
    int r = r_in ? r_in[0] : 1024;
    if (r < 0) r = 0;
    if (r > Sq/2) r = Sq/2;
    const int s_out = Sq - r;
    const int b = blockIdx.x / Sq;
    const int j = blockIdx.x - b*Sq;
    if (j >= s_out) return;

    const int packed = g_idxsel[b*Sq + j];
    const int i   = packed >> 1;
    const int sel = packed & 1;
    const size_t tin  = (size_t)b*Sq + i;
    const size_t tout = (size_t)b*s_out + j;

    const float4* x0 = (const float4*)(x + tin*Dq);
    float4* xo = (float4*)(out + tout*Dq);
    const float4* s0 = (const float4*)(src + tin*NOq);
    float4* so = (float4*)(out + (size_t)Bq*s_out*Dq + tout*NOq);

    if (sel){
        const float wi = g_gn[tin], wj = g_gn[tin+1];
        const float inv = 1.f / (wi + wj + 1e-8f);
        const float4* x1 = (const float4*)(x + (tin+1)*Dq);
        for (int t = threadIdx.x; t < Dq/4; t += 256){
            float4 a = x0[t], c = x1[t], o;
            o.x = (wi*a.x + wj*c.x)*inv; o.y = (wi*a.y + wj*c.y)*inv;
            o.z = (wi*a.z + wj*c.z)*inv; o.w = (wi*a.w + wj*c.w)*inv;
            xo[t] = o;
        }
        const float4* s1 = (const float4*)(src + (tin+1)*NOq);
        for (int t = threadIdx.x; t < NOq/4; t += 256){
            float4 a = s0[t], c = s1[t], o;
            o.x = a.x+c.x; o.y = a.y+c.y; o.z = a.z+c.z; o.w = a.w+c.w;
            so[t] = o;
        }
    } else {
        for (int t = threadIdx.x; t < Dq/4;  t += 256) xo[t] = x0[t];
        for (int t = threadIdx.x; t < NOq/4; t += 256) so[t] = s0[t];
    }
}

// ---------------- launch ----------------------------------------------------
extern "C" void kernel_launch(void* const* d_in, const int* in_sizes, int n_in,
                              void* d_out, int out_size){
    (void)in_sizes; (void)out_size;
    const float* x    = (const float*)d_in[0];
    const float* src  = (const float*)d_in[1];
    const int*   pos  = (const int*)d_in[2];
    const int*   span = (const int*)d_in[3];
    const float* W    = (const float*)d_in[4];
    const int*   r    = (n_in >= 6) ? (const int*)d_in[5] : nullptr;
    float* out = (float*)d_out;

    cudaFuncSetAttribute(k_gemm_tc, cudaFuncAttributeMaxDynamicSharedMemorySize, TC_SMEM);

    k_gemm_tc<<<128, 256, TC_SMEM>>>(x, W);
    k_bsim   <<<Bq, 992>>>();
    k_select <<<Bq, 1024, SEL_SMEM>>>(pos, span, r, out);
    k_gather <<<Bq*Sq, 256>>>(x, src, r, out);
}

// round 15
// speedup vs baseline: 2.4832x; 1.0730x over previous
#include <cuda_runtime.h>
#include <cuda_bf16.h>
#include <cstdint>

#define Bq 4
#define Sq 4096
#define Dq 768
#define GDq 64
#define NOq 4096
#define SM1q (Sq-1)
#define ROWSq (Bq*Sq)

typedef unsigned long long u64;
typedef unsigned int u32;
typedef unsigned short u16;

// ---------------- scratch (device globals: no allocations allowed) ----------
__device__ float g_gn[ROWSq];          // norms
__device__ float g_sim[Bq*SM1q];       // adjacent cosine sims
__device__ int   g_idxsel[ROWSq];      // per output slot: (src_index<<1)|sel
__device__ float g_brow0[256*64];      // normalized row 0 of each CTA
__device__ float g_brow1[256*64];      // normalized row 63 of each CTA

// ---------------- K0: g = x @ W^T via mma.sync bf16 (3-way split, 6 terms) --
// 256 CTAs x 256 thr, 2 CTAs/SM; CTA = 64 rows x 64 gd; K chunked by 128.
// Warp (wid&3) = m16 tile, (wid>>2) = n32 half. Co-resident CTAs overlap
// conversion (ALU) with MMA (tensor). Per-element HMMA order identical to
// the R13 kernel; norm/sim epilogue replays the exact old reduction order
// => bit-identical sims => identical selection.
#define OFF_AH 0
#define OFF_AM 16384
#define OFF_AL 32768
#define OFF_BH 49152
#define OFF_BM 65536
#define OFF_BL 81920
#define TC_SMEM 98304

__device__ __forceinline__ u32 smem_u32(const void* p){
    u32 a;
    asm("{ .reg .u64 t; cvta.to.shared.u64 t, %1; cvt.u32.u64 %0, t; }"
        : "=r"(a) : "l"(p));
    return a;
}

// row stride 256B (128 bf16). 16B-unit swizzle: unit ^= (row & 7)
__device__ __forceinline__ u32 tswz(int row, int kbyte){
    return (u32)(row*256 + ((((kbyte >> 4) ^ (row & 7))) << 4) + (kbyte & 15));
}

__device__ __forceinline__ void split3(float v, u16& h, u16& m, u16& l){
    __nv_bfloat16 bh = __float2bfloat16(v);
    float r1 = v - __bfloat162float(bh);
    __nv_bfloat16 bm = __float2bfloat16(r1);
    float r2 = r1 - __bfloat162float(bm);
    __nv_bfloat16 bl = __float2bfloat16(r2);
    h = __bfloat16_as_ushort(bh);
    m = __bfloat16_as_ushort(bm);
    l = __bfloat16_as_ushort(bl);
}

#define LDSM_X4(r0,r1,r2,r3,addr) \
    asm volatile("ldmatrix.sync.aligned.m8n8.x4.shared.b16 {%0,%1,%2,%3}, [%4];" \
        : "=r"(r0), "=r"(r1), "=r"(r2), "=r"(r3) : "r"(addr))

#define HMMA(d, a, b) \
    asm volatile("mma.sync.aligned.m16n8k16.row.col.f32.bf16.bf16.f32 " \
        "{%0,%1,%2,%3}, {%4,%5,%6,%7}, {%8,%9}, {%0,%1,%2,%3};" \
        : "+f"((d)[0]), "+f"((d)[1]), "+f"((d)[2]), "+f"((d)[3]) \
        : "r"((a)[0]), "r"((a)[1]), "r"((a)[2]), "r"((a)[3]), \
          "r"((b)[0]), "r"((b)[1]))

__global__ void __launch_bounds__(256, 2) k_gemm_tc(const float* __restrict__ x,
                                                    const float* __restrict__ W){
    extern __shared__ unsigned char sm[];
    const u32 sb = smem_u32(sm);
    const int tid  = threadIdx.x;
    const int wid  = tid >> 5, lane = tid & 31;
    const int rowBase = blockIdx.x * 64;
    const int m0 = (wid & 3) * 16;
    const int n0 = (wid >> 2) * 32;

    float acc[4][4];
    #pragma unroll
    for (int nt = 0; nt < 4; nt++)
        #pragma unroll
        for (int q = 0; q < 4; q++) acc[nt][q] = 0.f;

    const float4* xg = (const float4*)x;
    const float4* Wg = (const float4*)W;

    const int id   = lane >> 3;
    const int l8   = lane & 7;
    const int amr  = m0 + ((id & 1) << 3) + l8;
    const int akoff = (id >> 1) << 4;
    const int bnr0 = ((id >> 1) << 3) + l8;
    const int bkoff = (id & 1) << 4;

    for (int c = 0; c < 6; c++){
        if (c) __syncthreads();
        // ---- convert x chunk: 64 rows x 32 float4 ; 8 f4/thread ------------
        #pragma unroll
        for (int it = 0; it < 8; it++){
            int f   = tid + it*256;
            int row = f >> 5, k4 = f & 31;
            float4 v = xg[(size_t)(rowBase + row)*192 + c*32 + k4];
            u16 h0,h1,h2,h3, mm0,mm1,mm2,mm3, l0,l1,l2,l3;
            split3(v.x,h0,mm0,l0); split3(v.y,h1,mm1,l1);
            split3(v.z,h2,mm2,l2); split3(v.w,h3,mm3,l3);
            u32 so = tswz(row, k4*8);
            *(uint2*)(sm + OFF_AH + so) =
                make_uint2((u32)h0  | ((u32)h1 <<16), (u32)h2  | ((u32)h3 <<16));
            *(uint2*)(sm + OFF_AM + so) =
                make_uint2((u32)mm0 | ((u32)mm1<<16), (u32)mm2 | ((u32)mm3<<16));
            *(uint2*)(sm + OFF_AL + so) =
                make_uint2((u32)l0  | ((u32)l1 <<16), (u32)l2  | ((u32)l3 <<16));
        }
        // ---- convert W chunk: 64 rows x 32 float4 ; 8 f4/thread ------------
        #pragma unroll
        for (int it = 0; it < 8; it++){
            int f   = tid + it*256;
            int row = f >> 5, k4 = f & 31;
            float4 v = Wg[(size_t)row*192 + c*32 + k4];
            u16 h0,h1,h2,h3, mm0,mm1,mm2,mm3, l0,l1,l2,l3;
            split3(v.x,h0,mm0,l0); split3(v.y,h1,mm1,l1);
            split3(v.z,h2,mm2,l2); split3(v.w,h3,mm3,l3);
            u32 so = tswz(row, k4*8);
            *(uint2*)(sm + OFF_BH + so) =
                make_uint2((u32)h0  | ((u32)h1 <<16), (u32)h2  | ((u32)h3 <<16));
            *(uint2*)(sm + OFF_BM + so) =
                make_uint2((u32)mm0 | ((u32)mm1<<16), (u32)mm2 | ((u32)mm3<<16));
            *(uint2*)(sm + OFF_BL + so) =
                make_uint2((u32)l0  | ((u32)l1 <<16), (u32)l2  | ((u32)l3 <<16));
        }
        __syncthreads();

        #pragma unroll
        for (int ks = 0; ks < 8; ks++){
            const int kb = ks*32;
            u32 A[3][4];
            {
                u32 ao = tswz(amr, kb + akoff);
                LDSM_X4(A[0][0],A[0][1],A[0][2],A[0][3], sb + OFF_AH + ao);
                LDSM_X4(A[1][0],A[1][1],A[1][2],A[1][3], sb + OFF_AM + ao);
                LDSM_X4(A[2][0],A[2][1],A[2][2],A[2][3], sb + OFF_AL + ao);
            }
            u32 Bf[3][4][2];
            #pragma unroll
            for (int np = 0; np < 2; np++){
                u32 bo = tswz(n0 + np*16 + bnr0, kb + bkoff);
                u32 r0,r1,r2,r3;
                LDSM_X4(r0,r1,r2,r3, sb + OFF_BH + bo);
                Bf[0][np*2][0]=r0; Bf[0][np*2][1]=r1;
                Bf[0][np*2+1][0]=r2; Bf[0][np*2+1][1]=r3;
                LDSM_X4(r0,r1,r2,r3, sb + OFF_BM + bo);
                Bf[1][np*2][0]=r0; Bf[1][np*2][1]=r1;
                Bf[1][np*2+1][0]=r2; Bf[1][np*2+1][1]=r3;
                LDSM_X4(r0,r1,r2,r3, sb + OFF_BL + bo);
                Bf[2][np*2][0]=r0; Bf[2][np*2][1]=r1;
                Bf[2][np*2+1][0]=r2; Bf[2][np*2+1][1]=r3;
            }
            // same combo order as before: hh, hm, mh, hl, lh, mm
            #pragma unroll
            for (int nt = 0; nt < 4; nt++) HMMA(acc[nt], A[0], Bf[0][nt]);
            #pragma unroll
            for (int nt = 0; nt < 4; nt++) HMMA(acc[nt], A[0], Bf[1][nt]);
            #pragma unroll
            for (int nt = 0; nt < 4; nt++) HMMA(acc[nt], A[1], Bf[0][nt]);
            #pragma unroll
            for (int nt = 0; nt < 4; nt++) HMMA(acc[nt], A[0], Bf[2][nt]);
            #pragma unroll
            for (int nt = 0; nt < 4; nt++) HMMA(acc[nt], A[2], Bf[0][nt]);
            #pragma unroll
            for (int nt = 0; nt < 4; nt++) HMMA(acc[nt], A[1], Bf[1][nt]);
        }
    }

    // ---- epilogue: stage raw g to smem, replay old norm order exactly ------
    __syncthreads();                       // all tile reads done
    float* gu = (float*)sm;                // [64][64] raw then normalized rows
    {
        const int qr = lane >> 2;
        const int qc = lane & 3;
        const int r1l = m0 + qr;
        const int r2l = r1l + 8;
        #pragma unroll
        for (int nt = 0; nt < 4; nt++){
            *(float2*)(gu + r1l*64 + n0 + nt*8 + qc*2) =
                make_float2(acc[nt][0], acc[nt][1]);
            *(float2*)(gu + r2l*64 + n0 + nt*8 + qc*2) =
                make_float2(acc[nt][2], acc[nt][3]);
        }
    }
    __syncthreads();

    // norm warps 0-3: EXACT old per-lane fmaf chain over nt=0..7 + quad shfl
    if (wid < 4){
        const int qr = lane >> 2;
        const int qc = lane & 3;
        const int r1l = wid*16 + qr;
        const int r2l = r1l + 8;
        float v1[16], v2[16];
        #pragma unroll
        for (int nt = 0; nt < 8; nt++){
            float2 a = *(float2*)(gu + r1l*64 + nt*8 + qc*2);
            float2 b = *(float2*)(gu + r2l*64 + nt*8 + qc*2);
            v1[nt*2] = a.x; v1[nt*2+1] = a.y;
            v2[nt*2] = b.x; v2[nt*2+1] = b.y;
        }
        float s1 = 0.f, s2 = 0.f;
        #pragma unroll
        for (int nt = 0; nt < 8; nt++){
            s1 = fmaf(v1[nt*2],   v1[nt*2],   s1);
            s1 = fmaf(v1[nt*2+1], v1[nt*2+1], s1);
            s2 = fmaf(v2[nt*2],   v2[nt*2],   s2);
            s2 = fmaf(v2[nt*2+1], v2[nt*2+1], s2);
        }
        s1 += __shfl_xor_sync(0xffffffffu, s1, 1);
        s1 += __shfl_xor_sync(0xffffffffu, s1, 2);
        s2 += __shfl_xor_sync(0xffffffffu, s2, 1);
        s2 += __shfl_xor_sync(0xffffffffu, s2, 2);

        float n1 = __fsqrt_rn(s1), n2 = __fsqrt_rn(s2);
        if (qc == 0){ g_gn[rowBase + r1l] = n1; g_gn[rowBase + r2l] = n2; }
        float d1 = fmaxf(n1, 1e-12f), d2 = fmaxf(n2, 1e-12f);
        #pragma unroll
        for (int nt = 0; nt < 8; nt++){
            float2 o1, o2;
            o1.x = __fdiv_rn(v1[nt*2],   d1);
            o1.y = __fdiv_rn(v1[nt*2+1], d1);
            o2.x = __fdiv_rn(v2[nt*2],   d2);
            o2.y = __fdiv_rn(v2[nt*2+1], d2);
            *(float2*)(gu + r1l*64 + nt*8 + qc*2) = o1;
            *(float2*)(gu + r2l*64 + nt*8 + qc*2) = o2;
        }
    }
    __syncthreads();

    // in-CTA adjacent sims (63 pairs): identical warp-dot order
    {
        const int bIdx = rowBase >> 12;
        const int s0   = rowBase & 4095;
        for (int j = wid; j < 63; j += 8){
            const float* A  = gu + j*64;
            const float* Bv = gu + (j+1)*64;
            float v = fmaf(A[lane], Bv[lane], A[lane+32]*Bv[lane+32]);
            #pragma unroll
            for (int o = 16; o; o >>= 1) v += __shfl_xor_sync(0xffffffffu, v, o);
            if (!lane) g_sim[bIdx*SM1q + s0 + j] = v;
        }
    }
    // export boundary rows
    if (tid < 64)       g_brow0[blockIdx.x*64 + tid]        = gu[tid];
    else if (tid < 128) g_brow1[blockIdx.x*64 + (tid - 64)] = gu[63*64 + tid - 64];
}

// ---------------- K2: boundary sims + matching + cap + compaction -----------
#define SEL_SMEM 39168
__global__ void __launch_bounds__(1024) k_select(const int* __restrict__ pos_ids,
                                                 const int* __restrict__ span_ids,
                                                 const int* __restrict__ r_in,
                                                 float* __restrict__ out){
    extern __shared__ unsigned char smraw[];
    u64* key  = (u64*)smraw;                       // [4096]  32768 B
    unsigned char* ab  = smraw + 32768;            // [1024] alive bytes
    unsigned char* win = smraw + 33792;            // [4096] final selection
    int* hist = (int*)(smraw + 37888);             // [256]
    int* ibuf = (int*)(smraw + 38912);             // [32]
    u64* pfx  = (u64*)(smraw + 39040);             // [1]
    int* prnk = (int*)(smraw + 39048);             // [1]

    const int tid = threadIdx.x;
    const int b   = blockIdx.x;
    int r = r_in ? r_in[0] : 1024;
    if (r < 0) r = 0;
    if (r > Sq/2) r = Sq/2;
    const int s_out = Sq - r;
    const int p0 = tid*4;
    const int lane = tid & 31;
    const int wid  = tid >> 5;

    // ---- fused boundary sims: 63 per sequence, same warp-dot order ---------
    #pragma unroll
    for (int half = 0; half < 2; half++){
        int k = wid + half*32;
        if (k < 63){
            int c = b*64 + k;
            const float* A  = g_brow1 + c*64;
            const float* Bv = g_brow0 + (c+1)*64;
            float v = fmaf(A[lane], Bv[lane], A[lane+32]*Bv[lane+32]);
            #pragma unroll
            for (int o = 16; o; o >>= 1) v += __shfl_xor_sync(0xffffffffu, v, o);
            if (!lane) g_sim[b*SM1q + k*64 + 63] = v;
        }
    }
    __syncthreads();

    // strict-total-order keys: sim desc, index asc
    u64 k0,k1,k2,k3;
    bool a0,a1,a2,a3;
    {
        float4 sv;
        sv.x = (p0+0 < SM1q) ? g_sim[b*SM1q + p0+0] : 0.f;
        sv.y = (p0+1 < SM1q) ? g_sim[b*SM1q + p0+1] : 0.f;
        sv.z = (p0+2 < SM1q) ? g_sim[b*SM1q + p0+2] : 0.f;
        sv.w = (p0+3 < SM1q) ? g_sim[b*SM1q + p0+3] : 0.f;
        u32 u;
        u = __float_as_uint(sv.x); u = (u & 0x80000000u) ? ~u : (u | 0x80000000u);
        k0 = ((u64)u << 32) | (u32)(0xFFFFFFFFu - (u32)(p0+0));
        u = __float_as_uint(sv.y); u = (u & 0x80000000u) ? ~u : (u | 0x80000000u);
        k1 = ((u64)u << 32) | (u32)(0xFFFFFFFFu - (u32)(p0+1));
        u = __float_as_uint(sv.z); u = (u & 0x80000000u) ? ~u : (u | 0x80000000u);
        k2 = ((u64)u << 32) | (u32)(0xFFFFFFFFu - (u32)(p0+2));
        u = __float_as_uint(sv.w); u = (u & 0x80000000u) ? ~u : (u | 0x80000000u);
        k3 = ((u64)u << 32) | (u32)(0xFFFFFFFFu - (u32)(p0+3));
        a0 = (p0+0 < SM1q); a1 = (p0+1 < SM1q);
        a2 = (p0+2 < SM1q); a3 = (p0+3 < SM1q);
        if (!a3) k3 = 0ull;
    }
    key[p0+0] = k0; key[p0+1] = k1; key[p0+2] = k2; key[p0+3] = k3;
    __syncthreads();
    u64 lk2 = 0, lk3 = 0, rk0 = 0, rk1 = 0;
    if (tid > 0)    { lk2 = key[p0-2]; lk3 = key[p0-1]; }
    if (tid < 1023) { rk0 = key[p0+4]; rk1 = key[p0+5]; }

    bool s0=false, s1=false, s2=false, s3=false;

    while (true){
        ab[tid] = (unsigned char)((a0?1:0) | (a1?2:0) | (a2?4:0) | (a3?8:0));
        __syncthreads();
        unsigned char lab = (tid > 0)    ? ab[tid-1] : 0;
        unsigned char rab = (tid < 1023) ? ab[tid+1] : 0;
        bool la2 = lab & 4, la3 = lab & 8;
        bool ra0 = rab & 1, ra1 = rab & 2;

        bool w0 = a0 && !(la3 && lk3 > k0) && !(a1 && k1 > k0);
        bool w1 = a1 && !(a0 && k0 > k1) && !(a2 && k2 > k1);
        bool w2 = a2 && !(a1 && k1 > k2) && !(a3 && k3 > k2);
        bool w3 = a3 && !(a2 && k2 > k3) && !(ra0 && rk0 > k3);
        bool lw = la3 && !(la2 && lk2 > lk3) && !(a0 && k0 > lk3);
        bool rw = ra0 && !(a3 && k3 > rk0) && !(ra1 && rk1 > rk0);

        s0 |= w0; s1 |= w1; s2 |= w2; s3 |= w3;
        a0 = a0 && !w0 && !lw && !w1;
        a1 = a1 && !w1 && !w0 && !w2;
        a2 = a2 && !w2 && !w1 && !w3;
        a3 = a3 && !w3 && !w2 && !rw;

        int cont = __syncthreads_or((int)(a0|a1|a2|a3));
        if (!cont) break;
    }

    // exact radix select: thr = r-th largest selected key (keys distinct)
    u64 thr = ~0ull;
    if (r > 0){
        u64 prefix = 0; int rank = r;
        for (int lvl = 7; lvl >= 0; lvl--){
            const int shift = lvl*8;
            if (tid < 256) hist[tid] = 0;
            __syncthreads();
            {
                bool m0_ = s0 && ((lvl == 7) || ((k0 >> (shift+8)) == (prefix >> (shift+8))));
                bool m1_ = s1 && ((lvl == 7) || ((k1 >> (shift+8)) == (prefix >> (shift+8))));
                bool m2_ = s2 && ((lvl == 7) || ((k2 >> (shift+8)) == (prefix >> (shift+8))));
                bool m3_ = s3 && ((lvl == 7) || ((k3 >> (shift+8)) == (prefix >> (shift+8))));
                if (m0_) atomicAdd(&hist[(int)((k0 >> shift) & 255)], 1);
                if (m1_) atomicAdd(&hist[(int)((k1 >> shift) & 255)], 1);
                if (m2_) atomicAdd(&hist[(int)((k2 >> shift) & 255)], 1);
                if (m3_) atomicAdd(&hist[(int)((k3 >> shift) & 255)], 1);
            }
            __syncthreads();
            if (tid < 32){
                const int base = tid*8;
                int h[8]; int T = 0;
                #pragma unroll
                for (int q = 0; q < 8; q++){ h[q] = hist[base+q]; T += h[q]; }
                int S = T;
                #pragma unroll
                for (int o = 1; o < 32; o <<= 1){
                    int v = __shfl_down_sync(0xffffffffu, S, o);
                    if (tid + o < 32) S += v;
                }
                unsigned mask = __ballot_sync(0xffffffffu, S >= rank);
                int owner = 31 - __clz(mask);
                if (tid == owner){
                    int cum = S - T;
                    #pragma unroll
                    for (int q = 7; q >= 0; q--){
                        cum += h[q];
                        if (cum >= rank){
                            pfx[0]  = prefix | ((u64)(u32)(base + q) << shift);
                            prnk[0] = rank - (cum - h[q]);
                            break;
                        }
                    }
                }
            }
            __syncthreads();
            prefix = pfx[0]; rank = prnk[0];
        }
        thr = prefix;
    }

    const bool none = (r == 0);
    win[p0+0] = (!none && s0 && k0 >= thr) ? 1 : 0;
    win[p0+1] = (!none && s1 && k1 >= thr) ? 1 : 0;
    win[p0+2] = (!none && s2 && k2 >= thr) ? 1 : 0;
    win[p0+3] = (!none && s3 && k3 >= thr) ? 1 : 0;
    __syncthreads();

    // keep mask + block-wide exclusive scan (4 tokens / thread)
    const int i0 = tid * 4;
    int kf[4]; int lsum = 0;
    #pragma unroll
    for (int c = 0; c < 4; c++){
        int i = i0 + c;
        int kp = (i == 0) ? 1 : (win[i-1] ? 0 : 1);
        kf[c] = kp; lsum += kp;
    }
    int incl = lsum;
    #pragma unroll
    for (int o = 1; o < 32; o <<= 1){
        int v = __shfl_up_sync(0xffffffffu, incl, o);
        if (lane >= o) incl += v;
    }
    if (lane == 31) ibuf[wid] = incl;
    __syncthreads();
    if (tid < 32){
        int v = ibuf[tid];
        int inc2 = v;
        #pragma unroll
        for (int o = 1; o < 32; o <<= 1){
            int t2 = __shfl_up_sync(0xffffffffu, inc2, o);
            if (tid >= o) inc2 += t2;
        }
        ibuf[tid] = inc2 - v;
    }
    __syncthreads();
    int pos = ibuf[wid] + (incl - lsum);

    const size_t posBase  = (size_t)Bq * s_out * (Dq + NOq);
    const size_t spanBase = posBase + (size_t)Bq * s_out;
    #pragma unroll
    for (int c = 0; c < 4; c++){
        int i = i0 + c;
        if (kf[c]){
            if (pos < s_out){
                int sel = (i < SM1q && win[i]) ? 1 : 0;
                g_idxsel[b*Sq + pos] = (i << 1) | sel;
                out[posBase  + (size_t)b*s_out + pos] = (float)pos_ids[b*Sq + i];
                int sp = span_ids[b*Sq + i] + (sel ? span_ids[b*Sq + i + 1] : 0);
                out[spanBase + (size_t)b*s_out + pos] = (float)sp;
            }
            pos++;
        }
    }
}

// ---------------- K3: gather + weighted merge (the bandwidth kernel) --------
__global__ void __launch_bounds__(256) k_gather(const float* __restrict__ x,
                                                const float* __restrict__ src,
                                                const int* __restrict__ r_in,
                                                float* __restrict__ out){
    int r = r_in ? r_in[0] : 1024;
    if (r < 0) r = 0;
    if (r > Sq/2) r = Sq/2;
    const int s_out = Sq - r;
    const int b = blockIdx.x / Sq;
    const int j = blockIdx.x - b*Sq;
    if (j >= s_out) return;

    const int packed = g_idxsel[b*Sq + j];
    const int i   = packed >> 1;
    const int sel = packed & 1;
    const size_t tin  = (size_t)b*Sq + i;
    const size_t tout = (size_t)b*s_out + j;

    const float4* x0 = (const float4*)(x + tin*Dq);
    float4* xo = (float4*)(out + tout*Dq);
    const float4* s0 = (const float4*)(src + tin*NOq);
    float4* so = (float4*)(out + (size_t)Bq*s_out*Dq + tout*NOq);

    if (sel){
        const float wi = g_gn[tin], wj = g_gn[tin+1];
        const float inv = 1.f / (wi + wj + 1e-8f);
        const float4* x1 = (const float4*)(x + (tin+1)*Dq);
        for (int t = threadIdx.x; t < Dq/4; t += 256){
            float4 a = x0[t], c = x1[t], o;
            o.x = (wi*a.x + wj*c.x)*inv; o.y = (wi*a.y + wj*c.y)*inv;
            o.z = (wi*a.z + wj*c.z)*inv; o.w = (wi*a.w + wj*c.w)*inv;
            xo[t] = o;
        }
        const float4* s1 = (const float4*)(src + (tin+1)*NOq);
        for (int t = threadIdx.x; t < NOq/4; t += 256){
            float4 a = s0[t], c = s1[t], o;
            o.x = a.x+c.x; o.y = a.y+c.y; o.z = a.z+c.z; o.w = a.w+c.w;
            so[t] = o;
        }
    } else {
        for (int t = threadIdx.x; t < Dq/4;  t += 256) xo[t] = x0[t];
        for (int t = threadIdx.x; t < NOq/4; t += 256) so[t] = s0[t];
    }
}

// ---------------- launch ----------------------------------------------------
extern "C" void kernel_launch(void* const* d_in, const int* in_sizes, int n_in,
                              void* d_out, int out_size){
    (void)in_sizes; (void)out_size;
    const float* x    = (const float*)d_in[0];
    const float* src  = (const float*)d_in[1];
    const int*   pos  = (const int*)d_in[2];
    const int*   span = (const int*)d_in[3];
    const float* W    = (const float*)d_in[4];
    const int*   r    = (n_in >= 6) ? (const int*)d_in[5] : nullptr;
    float* out = (float*)d_out;

    cudaFuncSetAttribute(k_gemm_tc, cudaFuncAttributeMaxDynamicSharedMemorySize, TC_SMEM);

    k_gemm_tc<<<256, 256, TC_SMEM>>>(x, W);
    k_select <<<Bq, 1024, SEL_SMEM>>>(pos, span, r, out);
    k_gather <<<Bq*Sq, 256>>>(x, src, r, out);
}

// round 17
// speedup vs baseline: 2.4993x; 1.0065x over previous
#include <cuda_runtime.h>
#include <cuda_bf16.h>
#include <cstdint>

#define Bq 4
#define Sq 4096
#define Dq 768
#define GDq 64
#define NOq 4096
#define SM1q (Sq-1)
#define ROWSq (Bq*Sq)

typedef unsigned long long u64;
typedef unsigned int u32;
typedef unsigned short u16;

// ---------------- scratch (device globals: no allocations allowed) ----------
__device__ float g_gn[ROWSq];          // norms
__device__ float g_sim[Bq*SM1q];       // adjacent cosine sims
__device__ int   g_idxsel[ROWSq];      // per output slot: (src_index<<1)|sel
__device__ float g_brow0[256*64];      // normalized row 0 of each CTA
__device__ float g_brow1[256*64];      // normalized row 63 of each CTA

// ---------------- K0: g = x @ W^T via mma.sync bf16 (3-way split, 6 terms) --
// 256 CTAs x 256 thr, 2 CTAs/SM; CTA = 64 rows x 64 gd; K chunked by 64,
// DOUBLE-BUFFERED smem (2 x 48KB) + register prefetch of the next chunk:
// LDG latency drains under the MMA phase. Per-element HMMA accumulation
// order is identical to R15 (k16-step -> combo), so sims are bit-identical.
#define PL_AH 0
#define PL_AM 8192
#define PL_AL 16384
#define PL_BH 24576
#define PL_BM 32768
#define PL_BL 40960
#define BUF_SZ 49152
#define TC_SMEM 98304

__device__ __forceinline__ u32 smem_u32(const void* p){
    u32 a;
    asm("{ .reg .u64 t; cvta.to.shared.u64 t, %1; cvt.u32.u64 %0, t; }"
        : "=r"(a) : "l"(p));
    return a;
}

// row stride 128B (64 bf16). 16B-unit swizzle: unit ^= (row & 7)
__device__ __forceinline__ u32 tswz64(int row, int kbyte){
    return (u32)(row*128 + ((((kbyte >> 4) ^ (row & 7))) << 4) + (kbyte & 15));
}

__device__ __forceinline__ void split3(float v, u16& h, u16& m, u16& l){
    __nv_bfloat16 bh = __float2bfloat16(v);
    float r1 = v - __bfloat162float(bh);
    __nv_bfloat16 bm = __float2bfloat16(r1);
    float r2 = r1 - __bfloat162float(bm);
    __nv_bfloat16 bl = __float2bfloat16(r2);
    h = __bfloat16_as_ushort(bh);
    m = __bfloat16_as_ushort(bm);
    l = __bfloat16_as_ushort(bl);
}

#define LDSM_X4(r0,r1,r2,r3,addr) \
    asm volatile("ldmatrix.sync.aligned.m8n8.x4.shared.b16 {%0,%1,%2,%3}, [%4];" \
        : "=r"(r0), "=r"(r1), "=r"(r2), "=r"(r3) : "r"(addr))

#define HMMA(d, a, b) \
    asm volatile("mma.sync.aligned.m16n8k16.row.col.f32.bf16.bf16.f32 " \
        "{%0,%1,%2,%3}, {%4,%5,%6,%7}, {%8,%9}, {%0,%1,%2,%3};" \
        : "+f"((d)[0]), "+f"((d)[1]), "+f"((d)[2]), "+f"((d)[3]) \
        : "r"((a)[0]), "r"((a)[1]), "r"((a)[2]), "r"((a)[3]), \
          "r"((b)[0]), "r"((b)[1]))

__global__ void __launch_bounds__(256, 2) k_gemm_tc(const float* __restrict__ x,
                                                    const float* __restrict__ W){
    extern __shared__ unsigned char sm[];
    const u32 sb = smem_u32(sm);
    const int tid  = threadIdx.x;
    const int wid  = tid >> 5, lane = tid & 31;
    const int rowBase = blockIdx.x * 64;
    const int m0 = (wid & 3) * 16;
    const int n0 = (wid >> 2) * 32;

    float acc[4][4];
    #pragma unroll
    for (int nt = 0; nt < 4; nt++)
        #pragma unroll
        for (int q = 0; q < 4; q++) acc[nt][q] = 0.f;

    const float4* xg = (const float4*)x;
    const float4* Wg = (const float4*)W;

    const int id   = lane >> 3;
    const int l8   = lane & 7;
    const int amr  = m0 + ((id & 1) << 3) + l8;
    const int akoff = (id >> 1) << 4;
    const int bnr0 = ((id >> 1) << 3) + l8;
    const int bkoff = (id & 1) << 4;

    const int rowT = tid >> 4;        // 0..15 (row = it*16 + rowT)
    const int k4T  = tid & 15;        // float4 index within 64-elem chunk row

    float4 xr[4], wr[4];

    // ---- preload + convert chunk 0 into buffer 0 ---------------------------
    #pragma unroll
    for (int it = 0; it < 4; it++){
        xr[it] = xg[(size_t)(rowBase + it*16 + rowT)*192 + k4T];
        wr[it] = Wg[(size_t)(it*16 + rowT)*192 + k4T];
    }
    {
        unsigned char* bp = sm;
        #pragma unroll
        for (int it = 0; it < 4; it++){
            int row = it*16 + rowT;
            u32 so = tswz64(row, k4T*8);
            u16 h0,h1,h2,h3, mm0,mm1,mm2,mm3, l0,l1,l2,l3;
            split3(xr[it].x,h0,mm0,l0); split3(xr[it].y,h1,mm1,l1);
            split3(xr[it].z,h2,mm2,l2); split3(xr[it].w,h3,mm3,l3);
            *(uint2*)(bp + PL_AH + so) =
                make_uint2((u32)h0  | ((u32)h1 <<16), (u32)h2  | ((u32)h3 <<16));
            *(uint2*)(bp + PL_AM + so) =
                make_uint2((u32)mm0 | ((u32)mm1<<16), (u32)mm2 | ((u32)mm3<<16));
            *(uint2*)(bp + PL_AL + so) =
                make_uint2((u32)l0  | ((u32)l1 <<16), (u32)l2  | ((u32)l3 <<16));
            split3(wr[it].x,h0,mm0,l0); split3(wr[it].y,h1,mm1,l1);
            split3(wr[it].z,h2,mm2,l2); split3(wr[it].w,h3,mm3,l3);
            *(uint2*)(bp + PL_BH + so) =
                make_uint2((u32)h0  | ((u32)h1 <<16), (u32)h2  | ((u32)h3 <<16));
            *(uint2*)(bp + PL_BM + so) =
                make_uint2((u32)mm0 | ((u32)mm1<<16), (u32)mm2 | ((u32)mm3<<16));
            *(uint2*)(bp + PL_BL + so) =
                make_uint2((u32)l0  | ((u32)l1 <<16), (u32)l2  | ((u32)l3 <<16));
        }
    }
    __syncthreads();

    for (int c = 0; c < 12; c++){
        const u32 curBase = (u32)(c & 1) * BUF_SZ;
        // prefetch next chunk into regs; scoreboard drains under the MMAs
        if (c + 1 < 12){
            #pragma unroll
            for (int it = 0; it < 4; it++){
                xr[it] = xg[(size_t)(rowBase + it*16 + rowT)*192 + (c+1)*16 + k4T];
                wr[it] = Wg[(size_t)(it*16 + rowT)*192 + (c+1)*16 + k4T];
            }
        }
        // ---- MMA phase over current buffer (4 k16-steps) -------------------
        #pragma unroll
        for (int ks = 0; ks < 4; ks++){
            const int kb = ks*32;
            u32 A[3][4];
            {
                u32 ao = sb + curBase + tswz64(amr, kb + akoff);
                LDSM_X4(A[0][0],A[0][1],A[0][2],A[0][3], ao + PL_AH);
                LDSM_X4(A[1][0],A[1][1],A[1][2],A[1][3], ao + PL_AM);
                LDSM_X4(A[2][0],A[2][1],A[2][2],A[2][3], ao + PL_AL);
            }
            u32 Bf[3][4][2];
            #pragma unroll
            for (int np = 0; np < 2; np++){
                u32 bo = sb + curBase + tswz64(n0 + np*16 + bnr0, kb + bkoff);
                u32 r0,r1,r2,r3;
                LDSM_X4(r0,r1,r2,r3, bo + PL_BH);
                Bf[0][np*2][0]=r0; Bf[0][np*2][1]=r1;
                Bf[0][np*2+1][0]=r2; Bf[0][np*2+1][1]=r3;
                LDSM_X4(r0,r1,r2,r3, bo + PL_BM);
                Bf[1][np*2][0]=r0; Bf[1][np*2][1]=r1;
                Bf[1][np*2+1][0]=r2; Bf[1][np*2+1][1]=r3;
                LDSM_X4(r0,r1,r2,r3, bo + PL_BL);
                Bf[2][np*2][0]=r0; Bf[2][np*2][1]=r1;
                Bf[2][np*2+1][0]=r2; Bf[2][np*2+1][1]=r3;
            }
            // same combo order: hh, hm, mh, hl, lh, mm
            #pragma unroll
            for (int nt = 0; nt < 4; nt++) HMMA(acc[nt], A[0], Bf[0][nt]);
            #pragma unroll
            for (int nt = 0; nt < 4; nt++) HMMA(acc[nt], A[0], Bf[1][nt]);
            #pragma unroll
            for (int nt = 0; nt < 4; nt++) HMMA(acc[nt], A[1], Bf[0][nt]);
            #pragma unroll
            for (int nt = 0; nt < 4; nt++) HMMA(acc[nt], A[0], Bf[2][nt]);
            #pragma unroll
            for (int nt = 0; nt < 4; nt++) HMMA(acc[nt], A[2], Bf[0][nt]);
            #pragma unroll
            for (int nt = 0; nt < 4; nt++) HMMA(acc[nt], A[1], Bf[1][nt]);
        }
        // ---- convert next chunk into the other buffer ----------------------
        if (c + 1 < 12){
            __syncthreads();               // other buffer's readers (c-1) done
            unsigned char* bp = sm + ((c+1) & 1) * BUF_SZ;
            #pragma unroll
            for (int it = 0; it < 4; it++){
                int row = it*16 + rowT;
                u32 so = tswz64(row, k4T*8);
                u16 h0,h1,h2,h3, mm0,mm1,mm2,mm3, l0,l1,l2,l3;
                split3(xr[it].x,h0,mm0,l0); split3(xr[it].y,h1,mm1,l1);
                split3(xr[it].z,h2,mm2,l2); split3(xr[it].w,h3,mm3,l3);
                *(uint2*)(bp + PL_AH + so) =
                    make_uint2((u32)h0  | ((u32)h1 <<16), (u32)h2  | ((u32)h3 <<16));
                *(uint2*)(bp + PL_AM + so) =
                    make_uint2((u32)mm0 | ((u32)mm1<<16), (u32)mm2 | ((u32)mm3<<16));
                *(uint2*)(bp + PL_AL + so) =
                    make_uint2((u32)l0  | ((u32)l1 <<16), (u32)l2  | ((u32)l3 <<16));
                split3(wr[it].x,h0,mm0,l0); split3(wr[it].y,h1,mm1,l1);
                split3(wr[it].z,h2,mm2,l2); split3(wr[it].w,h3,mm3,l3);
                *(uint2*)(bp + PL_BH + so) =
                    make_uint2((u32)h0  | ((u32)h1 <<16), (u32)h2  | ((u32)h3 <<16));
                *(uint2*)(bp + PL_BM + so) =
                    make_uint2((u32)mm0 | ((u32)mm1<<16), (u32)mm2 | ((u32)mm3<<16));
                *(uint2*)(bp + PL_BL + so) =
                    make_uint2((u32)l0  | ((u32)l1 <<16), (u32)l2  | ((u32)l3 <<16));
            }
            __syncthreads();               // stores visible before next MMA
        }
    }

    // ---- epilogue: stage raw g to smem, replay old norm order exactly ------
    __syncthreads();                       // all tile reads done
    float* gu = (float*)sm;                // [64][64] raw then normalized rows
    {
        const int qr = lane >> 2;
        const int qc = lane & 3;
        const int r1l = m0 + qr;
        const int r2l = r1l + 8;
        #pragma unroll
        for (int nt = 0; nt < 4; nt++){
            *(float2*)(gu + r1l*64 + n0 + nt*8 + qc*2) =
                make_float2(acc[nt][0], acc[nt][1]);
            *(float2*)(gu + r2l*64 + n0 + nt*8 + qc*2) =
                make_float2(acc[nt][2], acc[nt][3]);
        }
    }
    __syncthreads();

    // norm warps 0-3: EXACT old per-lane fmaf chain over nt=0..7 + quad shfl
    if (wid < 4){
        const int qr = lane >> 2;
        const int qc = lane & 3;
        const int r1l = wid*16 + qr;
        const int r2l = r1l + 8;
        float v1[16], v2[16];
        #pragma unroll
        for (int nt = 0; nt < 8; nt++){
            float2 a = *(float2*)(gu + r1l*64 + nt*8 + qc*2);
            float2 b = *(float2*)(gu + r2l*64 + nt*8 + qc*2);
            v1[nt*2] = a.x; v1[nt*2+1] = a.y;
            v2[nt*2] = b.x; v2[nt*2+1] = b.y;
        }
        float s1 = 0.f, s2 = 0.f;
        #pragma unroll
        for (int nt = 0; nt < 8; nt++){
            s1 = fmaf(v1[nt*2],   v1[nt*2],   s1);
            s1 = fmaf(v1[nt*2+1], v1[nt*2+1], s1);
            s2 = fmaf(v2[nt*2],   v2[nt*2],   s2);
            s2 = fmaf(v2[nt*2+1], v2[nt*2+1], s2);
        }
        s1 += __shfl_xor_sync(0xffffffffu, s1, 1);
        s1 += __shfl_xor_sync(0xffffffffu, s1, 2);
        s2 += __shfl_xor_sync(0xffffffffu, s2, 1);
        s2 += __shfl_xor_sync(0xffffffffu, s2, 2);

        float n1 = __fsqrt_rn(s1), n2 = __fsqrt_rn(s2);
        if (qc == 0){ g_gn[rowBase + r1l] = n1; g_gn[rowBase + r2l] = n2; }
        float d1 = fmaxf(n1, 1e-12f), d2 = fmaxf(n2, 1e-12f);
        #pragma unroll
        for (int nt = 0; nt < 8; nt++){
            float2 o1, o2;
            o1.x = __fdiv_rn(v1[nt*2],   d1);
            o1.y = __fdiv_rn(v1[nt*2+1], d1);
            o2.x = __fdiv_rn(v2[nt*2],   d2);
            o2.y = __fdiv_rn(v2[nt*2+1], d2);
            *(float2*)(gu + r1l*64 + nt*8 + qc*2) = o1;
            *(float2*)(gu + r2l*64 + nt*8 + qc*2) = o2;
        }
    }
    __syncthreads();

    // in-CTA adjacent sims (63 pairs): identical warp-dot order
    {
        const int bIdx = rowBase >> 12;
        const int s0   = rowBase & 4095;
        for (int j = wid; j < 63; j += 8){
            const float* A  = gu + j*64;
            const float* Bv = gu + (j+1)*64;
            float v = fmaf(A[lane], Bv[lane], A[lane+32]*Bv[lane+32]);
            #pragma unroll
            for (int o = 16; o; o >>= 1) v += __shfl_xor_sync(0xffffffffu, v, o);
            if (!lane) g_sim[bIdx*SM1q + s0 + j] = v;
        }
    }
    // export boundary rows
    if (tid < 64)       g_brow0[blockIdx.x*64 + tid]        = gu[tid];
    else if (tid < 128) g_brow1[blockIdx.x*64 + (tid - 64)] = gu[63*64 + tid - 64];
}

// ---------------- K2: boundary sims + matching + cap + compaction -----------
#define SEL_SMEM 39168
__global__ void __launch_bounds__(1024) k_select(const int* __restrict__ pos_ids,
                                                 const int* __restrict__ span_ids,
                                                 const int* __restrict__ r_in,
                                                 float* __restrict__ out){
    extern __shared__ unsigned char smraw[];
    u64* key  = (u64*)smraw;                       // [4096]  32768 B
    unsigned char* ab  = smraw + 32768;            // [1024] alive bytes
    unsigned char* win = smraw + 33792;            // [4096] final selection
    int* hist = (int*)(smraw + 37888);             // [256]
    int* ibuf = (int*)(smraw + 38912);             // [32]
    u64* pfx  = (u64*)(smraw + 39040);             // [1]
    int* prnk = (int*)(smraw + 39048);             // [1]

    const int tid = threadIdx.x;
    const int b   = blockIdx.x;
    int r = r_in ? r_in[0] : 1024;
    if (r < 0) r = 0;
    if (r > Sq/2) r = Sq/2;
    const int s_out = Sq - r;
    const int p0 = tid*4;
    const int lane = tid & 31;
    const int wid  = tid >> 5;

    // ---- fused boundary sims: 63 per sequence, same warp-dot order ---------
    #pragma unroll
    for (int half = 0; half < 2; half++){
        int k = wid + half*32;
        if (k < 63){
            int c = b*64 + k;
            const float* A  = g_brow1 + c*64;
            const float* Bv = g_brow0 + (c+1)*64;
            float v = fmaf(A[lane], Bv[lane], A[lane+32]*Bv[lane+32]);
            #pragma unroll
            for (int o = 16; o; o >>= 1) v += __shfl_xor_sync(0xffffffffu, v, o);
            if (!lane) g_sim[b*SM1q + k*64 + 63] = v;
        }
    }
    __syncthreads();

    // strict-total-order keys: sim desc, index asc
    u64 k0,k1,k2,k3;
    bool a0,a1,a2,a3;
    {
        float4 sv;
        sv.x = (p0+0 < SM1q) ? g_sim[b*SM1q + p0+0] : 0.f;
        sv.y = (p0+1 < SM1q) ? g_sim[b*SM1q + p0+1] : 0.f;
        sv.z = (p0+2 < SM1q) ? g_sim[b*SM1q + p0+2] : 0.f;
        sv.w = (p0+3 < SM1q) ? g_sim[b*SM1q + p0+3] : 0.f;
        u32 u;
        u = __float_as_uint(sv.x); u = (u & 0x80000000u) ? ~u : (u | 0x80000000u);
        k0 = ((u64)u << 32) | (u32)(0xFFFFFFFFu - (u32)(p0+0));
        u = __float_as_uint(sv.y); u = (u & 0x80000000u) ? ~u : (u | 0x80000000u);
        k1 = ((u64)u << 32) | (u32)(0xFFFFFFFFu - (u32)(p0+1));
        u = __float_as_uint(sv.z); u = (u & 0x80000000u) ? ~u : (u | 0x80000000u);
        k2 = ((u64)u << 32) | (u32)(0xFFFFFFFFu - (u32)(p0+2));
        u = __float_as_uint(sv.w); u = (u & 0x80000000u) ? ~u : (u | 0x80000000u);
        k3 = ((u64)u << 32) | (u32)(0xFFFFFFFFu - (u32)(p0+3));
        a0 = (p0+0 < SM1q); a1 = (p0+1 < SM1q);
        a2 = (p0+2 < SM1q); a3 = (p0+3 < SM1q);
        if (!a3) k3 = 0ull;
    }
    key[p0+0] = k0; key[p0+1] = k1; key[p0+2] = k2; key[p0+3] = k3;
    __syncthreads();
    u64 lk2 = 0, lk3 = 0, rk0 = 0, rk1 = 0;
    if (tid > 0)    { lk2 = key[p0-2]; lk3 = key[p0-1]; }
    if (tid < 1023) { rk0 = key[p0+4]; rk1 = key[p0+5]; }

    bool s0=false, s1=false, s2=false, s3=false;

    while (true){
        ab[tid] = (unsigned char)((a0?1:0) | (a1?2:0) | (a2?4:0) | (a3?8:0));
        __syncthreads();
        unsigned char lab = (tid > 0)    ? ab[tid-1] : 0;
        unsigned char rab = (tid < 1023) ? ab[tid+1] : 0;
        bool la2 = lab & 4, la3 = lab & 8;
        bool ra0 = rab & 1, ra1 = rab & 2;

        bool w0 = a0 && !(la3 && lk3 > k0) && !(a1 && k1 > k0);
        bool w1 = a1 && !(a0 && k0 > k1) && !(a2 && k2 > k1);
        bool w2 = a2 && !(a1 && k1 > k2) && !(a3 && k3 > k2);
        bool w3 = a3 && !(a2 && k2 > k3) && !(ra0 && rk0 > k3);
        bool lw = la3 && !(la2 && lk2 > lk3) && !(a0 && k0 > lk3);
        bool rw = ra0 && !(a3 && k3 > rk0) && !(ra1 && rk1 > rk0);

        s0 |= w0; s1 |= w1; s2 |= w2; s3 |= w3;
        a0 = a0 && !w0 && !lw && !w1;
        a1 = a1 && !w1 && !w0 && !w2;
        a2 = a2 && !w2 && !w1 && !w3;
        a3 = a3 && !w3 && !w2 && !rw;

        int cont = __syncthreads_or((int)(a0|a1|a2|a3));
        if (!cont) break;
    }

    // exact radix select: thr = r-th largest selected key (keys distinct)
    u64 thr = ~0ull;
    if (r > 0){
        u64 prefix = 0; int rank = r;
        for (int lvl = 7; lvl >= 0; lvl--){
            const int shift = lvl*8;
            if (tid < 256) hist[tid] = 0;
            __syncthreads();
            {
                bool m0_ = s0 && ((lvl == 7) || ((k0 >> (shift+8)) == (prefix >> (shift+8))));
                bool m1_ = s1 && ((lvl == 7) || ((k1 >> (shift+8)) == (prefix >> (shift+8))));
                bool m2_ = s2 && ((lvl == 7) || ((k2 >> (shift+8)) == (prefix >> (shift+8))));
                bool m3_ = s3 && ((lvl == 7) || ((k3 >> (shift+8)) == (prefix >> (shift+8))));
                if (m0_) atomicAdd(&hist[(int)((k0 >> shift) & 255)], 1);
                if (m1_) atomicAdd(&hist[(int)((k1 >> shift) & 255)], 1);
                if (m2_) atomicAdd(&hist[(int)((k2 >> shift) & 255)], 1);
                if (m3_) atomicAdd(&hist[(int)((k3 >> shift) & 255)], 1);
            }
            __syncthreads();
            if (tid < 32){
                const int base = tid*8;
                int h[8]; int T = 0;
                #pragma unroll
                for (int q = 0; q < 8; q++){ h[q] = hist[base+q]; T += h[q]; }
                int S = T;
                #pragma unroll
                for (int o = 1; o < 32; o <<= 1){
                    int v = __shfl_down_sync(0xffffffffu, S, o);
                    if (tid + o < 32) S += v;
                }
                unsigned mask = __ballot_sync(0xffffffffu, S >= rank);
                int owner = 31 - __clz(mask);
                if (tid == owner){
                    int cum = S - T;
                    #pragma unroll
                    for (int q = 7; q >= 0; q--){
                        cum += h[q];
                        if (cum >= rank){
                            pfx[0]  = prefix | ((u64)(u32)(base + q) << shift);
                            prnk[0] = rank - (cum - h[q]);
                            break;
                        }
                    }
                }
            }
            __syncthreads();
            prefix = pfx[0]; rank = prnk[0];
        }
        thr = prefix;
    }

    const bool none = (r == 0);
    win[p0+0] = (!none && s0 && k0 >= thr) ? 1 : 0;
    win[p0+1] = (!none && s1 && k1 >= thr) ? 1 : 0;
    win[p0+2] = (!none && s2 && k2 >= thr) ? 1 : 0;
    win[p0+3] = (!none && s3 && k3 >= thr) ? 1 : 0;
    __syncthreads();

    // keep mask + block-wide exclusive scan (4 tokens / thread)
    const int i0 = tid * 4;
    int kf[4]; int lsum = 0;
    #pragma unroll
    for (int c = 0; c < 4; c++){
        int i = i0 + c;
        int kp = (i == 0) ? 1 : (win[i-1] ? 0 : 1);
        kf[c] = kp; lsum += kp;
    }
    int incl = lsum;
    #pragma unroll
    for (int o = 1; o < 32; o <<= 1){
        int v = __shfl_up_sync(0xffffffffu, incl, o);
        if (lane >= o) incl += v;
    }
    if (lane == 31) ibuf[wid] = incl;
    __syncthreads();
    if (tid < 32){
        int v = ibuf[tid];
        int inc2 = v;
        #pragma unroll
        for (int o = 1; o < 32; o <<= 1){
            int t2 = __shfl_up_sync(0xffffffffu, inc2, o);
            if (tid >= o) inc2 += t2;
        }
        ibuf[tid] = inc2 - v;
    }
    __syncthreads();
    int pos = ibuf[wid] + (incl - lsum);

    const size_t posBase  = (size_t)Bq * s_out * (Dq + NOq);
    const size_t spanBase = posBase + (size_t)Bq * s_out;
    #pragma unroll
    for (int c = 0; c < 4; c++){
        int i = i0 + c;
        if (kf[c]){
            if (pos < s_out){
                int sel = (i < SM1q && win[i]) ? 1 : 0;
                g_idxsel[b*Sq + pos] = (i << 1) | sel;
                out[posBase  + (size_t)b*s_out + pos] = (float)pos_ids[b*Sq + i];
                int sp = span_ids[b*Sq + i] + (sel ? span_ids[b*Sq + i + 1] : 0);
                out[spanBase + (size_t)b*s_out + pos] = (float)sp;
            }
            pos++;
        }
    }
}

// ---------------- K3: gather + weighted merge (the bandwidth kernel) --------
__global__ void __launch_bounds__(256) k_gather(const float* __restrict__ x,
                                                const float* __restrict__ src,
                                                const int* __restrict__ r_in,
                                                float* __restrict__ out){
    int r = r_in ? r_in[0] : 1024;
    if (r < 0) r = 0;
    if (r > Sq/2) r = Sq/2;
    const int s_out = Sq - r;
    const int b = blockIdx.x / Sq;
    const int j = blockIdx.x - b*Sq;
    if (j >= s_out) return;

    const int packed = g_idxsel[b*Sq + j];
    const int i   = packed >> 1;
    const int sel = packed & 1;
    const size_t tin  = (size_t)b*Sq + i;
    const size_t tout = (size_t)b*s_out + j;

    const float4* x0 = (const float4*)(x + tin*Dq);
    float4* xo = (float4*)(out + tout*Dq);
    const float4* s0 = (const float4*)(src + tin*NOq);
    float4* so = (float4*)(out + (size_t)Bq*s_out*Dq + tout*NOq);

    if (sel){
        const float wi = g_gn[tin], wj = g_gn[tin+1];
        const float inv = 1.f / (wi + wj + 1e-8f);
        const float4* x1 = (const float4*)(x + (tin+1)*Dq);
        for (int t = threadIdx.x; t < Dq/4; t += 256){
            float4 a = x0[t], c = x1[t], o;
            o.x = (wi*a.x + wj*c.x)*inv; o.y = (wi*a.y + wj*c.y)*inv;
            o.z = (wi*a.z + wj*c.z)*inv; o.w = (wi*a.w + wj*c.w)*inv;
            xo[t] = o;
        }
        const float4* s1 = (const float4*)(src + (tin+1)*NOq);
        for (int t = threadIdx.x; t < NOq/4; t += 256){
            float4 a = s0[t], c = s1[t], o;
            o.x = a.x+c.x; o.y = a.y+c.y; o.z = a.z+c.z; o.w = a.w+c.w;
            so[t] = o;
        }
    } else {
        for (int t = threadIdx.x; t < Dq/4;  t += 256) xo[t] = x0[t];
        for (int t = threadIdx.x; t < NOq/4; t += 256) so[t] = s0[t];
    }
}

// ---------------- launch ----------------------------------------------------
extern "C" void kernel_launch(void* const* d_in, const int* in_sizes, int n_in,
                              void* d_out, int out_size){
    (void)in_sizes; (void)out_size;
    const float* x    = (const float*)d_in[0];
    const float* src  = (const float*)d_in[1];
    const int*   pos  = (const int*)d_in[2];
    const int*   span = (const int*)d_in[3];
    const float* W    = (const float*)d_in[4];
    const int*   r    = (n_in >= 6) ? (const int*)d_in[5] : nullptr;
    float* out = (float*)d_out;

    cudaFuncSetAttribute(k_gemm_tc, cudaFuncAttributeMaxDynamicSharedMemorySize, TC_SMEM);

    k_gemm_tc<<<256, 256, TC_SMEM>>>(x, W);
    k_select <<<Bq, 1024, SEL_SMEM>>>(pos, span, r, out);
    k_gather <<<Bq*Sq, 256>>>(x, src, r, out);
}